// round 6
// baseline (speedup 1.0000x reference)
#include <cuda_runtime.h>
#include <math.h>

#define NMAX 50000
#define EMAX 500000
typedef unsigned long long ull;

// ---------------- static scratch ----------------
__device__ float  g_t  [(size_t)256 * EMAX];
__device__ float  g_xn [(size_t)128 * NMAX];
__device__ float  g_yAT[(size_t)256 * NMAX];   // (wEa @ xn)^T, node-major [n][256]
__device__ float  g_si [(size_t)128 * NMAX];
__device__ float  g_sj [(size_t)128 * NMAX];
// k-major weights
__device__ float  g_wEa[4 * 128 * 256];
__device__ float  g_wEb[4 * 128 * 256];
__device__ float  g_wNi[4 * 128 * 256];
__device__ float  g_wNj[4 * 128 * 256];
__device__ float  g_wNn[4 * 128 * 256];
__device__ float  g_wE2[4 * 256 * 128];
__device__ float  g_wN2[4 * 256 * 128];
__device__ float  g_k1n[32 * 128];
__device__ float  g_k2n[128 * 128];
__device__ float  g_k1e[32 * 128];
__device__ float  g_k2e[128 * 128];
__device__ float  g_ko [128 * 128];
__device__ double g_acc[20];

// ---------------- f32x2 helpers ----------------
__device__ __forceinline__ ull dup2(float v) {
    ull r; asm("mov.b64 %0, {%1, %1};" : "=l"(r) : "f"(v)); return r;
}
__device__ __forceinline__ ull pack2(float lo, float hi) {
    ull r; asm("mov.b64 %0, {%1, %2};" : "=l"(r) : "f"(lo), "f"(hi)); return r;
}
__device__ __forceinline__ void ffma2(ull& d, ull a, ull b) {
    asm("fma.rn.f32x2 %0, %1, %2, %0;" : "+l"(d) : "l"(a), "l"(b));
}
__device__ __forceinline__ float2 f2of(ull u) {
    union { ull u; float2 f; } cv; cv.u = u; return cv.f;
}

// ---------------- weight prep ----------------
__global__ void prep_kernelA(const float* __restrict__ KE1, const float* __restrict__ KN1,
                             const float* __restrict__ KE2, const float* __restrict__ KN2)
{
    int idx = blockIdx.x * blockDim.x + threadIdx.x;
    if (idx >= 4 * 128 * 256) return;
    int l = idx >> 15;
    int r = idx & 32767;
    {
        int o = r & 255, k = r >> 8;
        size_t src = ((size_t)l * 256 + o) * 384;
        int dst = (l << 15) + k * 256 + o;
        const float* e = KE1 + src;
        const float* n = KN1 + src;
        g_wEa[dst] = e[k] + e[128 + k];
        g_wEb[dst] = e[256 + k];
        float a = n[k], b = n[128 + k];
        g_wNi[dst] = 0.5f * a + b;
        g_wNj[dst] = 0.5f * a - b;
        g_wNn[dst] = n[256 + k];
    }
    {
        int o = r & 127, k = r >> 7;
        int dst = (l << 15) + k * 128 + o;
        g_wE2[dst] = KE2[((size_t)l * 128 + o) * 256 + k];
        g_wN2[dst] = KN2[((size_t)l * 128 + o) * 256 + k];
    }
}

__global__ void prep_kernelB(const float* __restrict__ K1No, const float* __restrict__ K2No,
                             const float* __restrict__ K1Eo, const float* __restrict__ K2Eo,
                             const float* __restrict__ KNout)
{
    int idx = blockIdx.x * blockDim.x + threadIdx.x;
    if (idx >= 128 * 128) return;
    int o = idx & 127, k = idx >> 7;
    if (k < 32) {
        g_k1n[k * 128 + o] = K1No[o * 32 + k];
        g_k1e[k * 128 + o] = K1Eo[o * 32 + k];
    }
    g_k2n[k * 128 + o] = K2No[o * 128 + k];
    g_k2e[k * 128 + o] = K2Eo[o * 128 + k];
    g_ko [k * 128 + o] = (o < 64) ? KNout[o * 128 + k] : 0.f;
}

// ---------------- fused f32x2 GEMM ----------------
// acc init from gInit (node-major gather) if given; up to 3 dense K-pairs;
// optional norm+relu on X; optional stats; epi: 0 store, 1 +=0.1, 2 +=0.1+scatter, 3 transposed store.
__global__ void __launch_bounds__(256, 2)
mm4_kernel(int M, int Oact, int Nn,
           const float* __restrict__ W0, const float* __restrict__ X0, int K0, int ld0, int ldW0,
           const float* __restrict__ W1, const float* __restrict__ X1, int K1, int ld1, int ldW1,
           const float* __restrict__ W2, const float* __restrict__ X2, int K2, int ld2, int ldW2,
           const float* __restrict__ gInit, const int* __restrict__ g0,
           const double* __restrict__ normAcc, double cntInv,
           double* __restrict__ statAcc,
           float* __restrict__ Y, int epi,
           float* __restrict__ si, float* __restrict__ sj,
           const int* __restrict__ iI, const int* __restrict__ jI)
{
    __shared__ __align__(16) ull   Wd[2][8][132];
    __shared__ __align__(16) float Xs[2][8][132];
    __shared__ int gidx[128], idxI[128], idxJ[128];

    const int tid  = threadIdx.x;
    const int m0   = blockIdx.x * 128;
    const int wb   = blockIdx.y * 128;
    const int lane = tid & 31;
    const int warp = tid >> 5;
    const int wrow = warp >> 2, wcol = warp & 3;
    const int col_t = lane & 3, row_t = lane >> 2;
    const int rbase = wrow * 64 + row_t * 4;
    const int cbase = wcol * 32 + col_t * 4;

    const int kkS = tid >> 5;
    const int mfS = (tid & 31) * 4;

    float mean = 0.f, inv = 0.f;
    const bool donorm = (normAcc != nullptr);
    if (donorm) {
        double mu = normAcc[0] * cntInv;
        double va = normAcc[1] * cntInv - mu * mu;
        mean = (float)mu;
        inv  = (float)rsqrt(va + 1e-5);
    }

    if (gInit)
        for (int i = tid; i < 128; i += 256) { int m = m0 + i; gidx[i] = (m < M) ? g0[m] : 0; }
    if (epi == 2)
        for (int i = tid; i < 128; i += 256) {
            int m = m0 + i;
            idxI[i] = (m < M) ? iI[m] : 0;
            idxJ[i] = (m < M) ? jI[m] : 0;
        }
    __syncthreads();

    ull acc[8][4];
    if (gInit) {
        #pragma unroll
        for (int j = 0; j < 4; j++) {
            int cA = cbase + (j >> 1) * 16 + (j & 1) * 2;
            int gA = gidx[cA], gB = gidx[cA + 1];
            const float* pA = gInit + (size_t)gA * 256 + wb + rbase;
            const float* pB = gInit + (size_t)gB * 256 + wb + rbase;
            float4 a0 = *(const float4*)(pA);
            float4 a1 = *(const float4*)(pA + 32);
            float4 b0 = *(const float4*)(pB);
            float4 b1 = *(const float4*)(pB + 32);
            acc[0][j] = pack2(a0.x, b0.x);
            acc[1][j] = pack2(a0.y, b0.y);
            acc[2][j] = pack2(a0.z, b0.z);
            acc[3][j] = pack2(a0.w, b0.w);
            acc[4][j] = pack2(a1.x, b1.x);
            acc[5][j] = pack2(a1.y, b1.y);
            acc[6][j] = pack2(a1.z, b1.z);
            acc[7][j] = pack2(a1.w, b1.w);
        }
    } else {
        #pragma unroll
        for (int r = 0; r < 8; r++)
            #pragma unroll
            for (int c = 0; c < 4; c++) acc[r][c] = 0ull;
    }

    const int c0 = K0 >> 3;
    const int c1 = W1 ? (K1 >> 3) : 0;
    const int c2 = W2 ? (K2 >> 3) : 0;
    const int totT = c0 + c1 + c2;

    auto ldgTile = [&](int t, float4& wv, float4& xv) {
        const float *W, *X; int ld, ldW, k0;
        if (t < c0)           { W = W0; X = X0; ld = ld0; ldW = ldW0; k0 = t * 8; }
        else if (t < c0 + c1) { W = W1; X = X1; ld = ld1; ldW = ldW1; k0 = (t - c0) * 8; }
        else                  { W = W2; X = X2; ld = ld2; ldW = ldW2; k0 = (t - c0 - c1) * 8; }
        wv = *(const float4*)(W + (size_t)(k0 + kkS) * ldW + wb + mfS);
        int m = m0 + mfS;
        if (m < M) {
            float4 v = *(const float4*)(X + (size_t)(k0 + kkS) * ld + m);
            if (donorm) {
                v.x = fmaxf((v.x - mean) * inv, 0.f);
                v.y = fmaxf((v.y - mean) * inv, 0.f);
                v.z = fmaxf((v.z - mean) * inv, 0.f);
                v.w = fmaxf((v.w - mean) * inv, 0.f);
            }
            xv = v;
        } else xv = make_float4(0.f, 0.f, 0.f, 0.f);
    };

    auto stsTile = [&](int buf, const float4& wv, const float4& xv) {
        ull* wr = &Wd[buf][kkS][mfS];
        wr[0] = dup2(wv.x); wr[1] = dup2(wv.y); wr[2] = dup2(wv.z); wr[3] = dup2(wv.w);
        *(float4*)&Xs[buf][kkS][mfS] = xv;
    };

    {
        float4 wv, xv;
        ldgTile(0, wv, xv);
        stsTile(0, wv, xv);
    }
    __syncthreads();

    float4 wpv, xpv;
    for (int t = 0; t < totT; t++) {
        const int cur = t & 1;
        const bool more = (t + 1 < totT);
        if (more) ldgTile(t + 1, wpv, xpv);

        #pragma unroll
        for (int kk = 0; kk < 8; kk++) {
            ulonglong2 w01 = *(const ulonglong2*)&Wd[cur][kk][rbase];
            ulonglong2 w23 = *(const ulonglong2*)&Wd[cur][kk][rbase + 2];
            ulonglong2 w45 = *(const ulonglong2*)&Wd[cur][kk][rbase + 32];
            ulonglong2 w67 = *(const ulonglong2*)&Wd[cur][kk][rbase + 34];
            ulonglong2 xa = *(const ulonglong2*)&Xs[cur][kk][cbase];
            ulonglong2 xb = *(const ulonglong2*)&Xs[cur][kk][cbase + 16];
            ffma2(acc[0][0], w01.x, xa.x); ffma2(acc[0][1], w01.x, xa.y); ffma2(acc[0][2], w01.x, xb.x); ffma2(acc[0][3], w01.x, xb.y);
            ffma2(acc[1][0], w01.y, xa.x); ffma2(acc[1][1], w01.y, xa.y); ffma2(acc[1][2], w01.y, xb.x); ffma2(acc[1][3], w01.y, xb.y);
            ffma2(acc[2][0], w23.x, xa.x); ffma2(acc[2][1], w23.x, xa.y); ffma2(acc[2][2], w23.x, xb.x); ffma2(acc[2][3], w23.x, xb.y);
            ffma2(acc[3][0], w23.y, xa.x); ffma2(acc[3][1], w23.y, xa.y); ffma2(acc[3][2], w23.y, xb.x); ffma2(acc[3][3], w23.y, xb.y);
            ffma2(acc[4][0], w45.x, xa.x); ffma2(acc[4][1], w45.x, xa.y); ffma2(acc[4][2], w45.x, xb.x); ffma2(acc[4][3], w45.x, xb.y);
            ffma2(acc[5][0], w45.y, xa.x); ffma2(acc[5][1], w45.y, xa.y); ffma2(acc[5][2], w45.y, xb.x); ffma2(acc[5][3], w45.y, xb.y);
            ffma2(acc[6][0], w67.x, xa.x); ffma2(acc[6][1], w67.x, xa.y); ffma2(acc[6][2], w67.x, xb.x); ffma2(acc[6][3], w67.x, xb.y);
            ffma2(acc[7][0], w67.y, xa.x); ffma2(acc[7][1], w67.y, xa.y); ffma2(acc[7][2], w67.y, xb.x); ffma2(acc[7][3], w67.y, xb.y);
        }

        if (more) stsTile(cur ^ 1, wpv, xpv);
        __syncthreads();
    }

    // ----- layernorm stats (producer) -----
    if (statAcc) {
        float s = 0.f, q = 0.f;
        #pragma unroll
        for (int r = 0; r < 8; r++)
            #pragma unroll
            for (int cg = 0; cg < 2; cg++) {
                if (m0 + cbase + cg * 16 < M) {
                    float2 v0 = f2of(acc[r][cg * 2 + 0]);
                    float2 v1 = f2of(acc[r][cg * 2 + 1]);
                    s += v0.x + v0.y + v1.x + v1.y;
                    q += v0.x * v0.x + v0.y * v0.y + v1.x * v1.x + v1.y * v1.y;
                }
            }
        __syncthreads();
        float* redS = (float*)Wd;
        float* redQ = ((float*)Wd) + 256;
        redS[tid] = s; redQ[tid] = q;
        __syncthreads();
        for (int st = 128; st > 0; st >>= 1) {
            if (tid < st) { redS[tid] += redS[tid + st]; redQ[tid] += redQ[tid + st]; }
            __syncthreads();
        }
        if (tid == 0) {
            atomicAdd(statAcc,     (double)redS[0]);
            atomicAdd(statAcc + 1, (double)redQ[0]);
        }
    }

    // ----- epilogue -----
    if (epi == 3) {
        // transposed store: Y[m][256], rows wb+rbase(+32)
        #pragma unroll
        for (int j = 0; j < 4; j++) {
            #pragma unroll
            for (int h = 0; h < 2; h++) {
                int c = m0 + cbase + (j >> 1) * 16 + (j & 1) * 2 + h;
                if (c >= M) continue;
                float4 v0, v1;
                if (h == 0) {
                    v0 = make_float4(f2of(acc[0][j]).x, f2of(acc[1][j]).x, f2of(acc[2][j]).x, f2of(acc[3][j]).x);
                    v1 = make_float4(f2of(acc[4][j]).x, f2of(acc[5][j]).x, f2of(acc[6][j]).x, f2of(acc[7][j]).x);
                } else {
                    v0 = make_float4(f2of(acc[0][j]).y, f2of(acc[1][j]).y, f2of(acc[2][j]).y, f2of(acc[3][j]).y);
                    v1 = make_float4(f2of(acc[4][j]).y, f2of(acc[5][j]).y, f2of(acc[6][j]).y, f2of(acc[7][j]).y);
                }
                float* dst = Y + (size_t)c * 256 + wb + rbase;
                *(float4*)(dst)      = v0;
                *(float4*)(dst + 32) = v1;
            }
        }
        return;
    }

    #pragma unroll
    for (int r = 0; r < 8; r++) {
        int lrow = (r < 4) ? (rbase + r) : (rbase + 32 + r - 4);
        int o = wb + lrow;
        if (o >= Oact) continue;
        #pragma unroll
        for (int cg = 0; cg < 2; cg++) {
            int c = m0 + cbase + cg * 16;
            if (c >= M) continue;
            float2 p0 = f2of(acc[r][cg * 2 + 0]);
            float2 p1 = f2of(acc[r][cg * 2 + 1]);
            size_t off = (size_t)o * M + c;
            if (epi == 0) {
                *(float4*)(Y + off) = make_float4(p0.x, p0.y, p1.x, p1.y);
            } else {
                float4 old = *(float4*)(Y + off);
                old.x += 0.1f * p0.x; old.y += 0.1f * p0.y;
                old.z += 0.1f * p1.x; old.w += 0.1f * p1.y;
                *(float4*)(Y + off) = old;
                if (epi == 2) {
                    int lc = cbase + cg * 16;
                    atomicAdd(si + (size_t)o * Nn + idxI[lc + 0], p0.x);
                    atomicAdd(si + (size_t)o * Nn + idxI[lc + 1], p0.y);
                    atomicAdd(si + (size_t)o * Nn + idxI[lc + 2], p1.x);
                    atomicAdd(si + (size_t)o * Nn + idxI[lc + 3], p1.y);
                    atomicAdd(sj + (size_t)o * Nn + idxJ[lc + 0], p0.x);
                    atomicAdd(sj + (size_t)o * Nn + idxJ[lc + 1], p0.y);
                    atomicAdd(sj + (size_t)o * Nn + idxJ[lc + 2], p1.x);
                    atomicAdd(sj + (size_t)o * Nn + idxJ[lc + 3], p1.y);
                }
            }
        }
    }
}

// ---------------- host-side dispatch ----------------
static inline void mm_launch(int gridy, int M, int Oact,
    const float* W0, const float* X0, int K0, int ld0, int ldW0,
    const float* W1, const float* X1, int K1, int ld1, int ldW1,
    const float* W2, const float* X2, int K2, int ld2, int ldW2,
    const float* gInit, const int* g0,
    const double* nAcc, double cntInv, double* sAcc,
    float* Y, int epi, float* si, float* sj, const int* iI, const int* jI, int Nn)
{
    dim3 grid((M + 127) / 128, gridy);
    mm4_kernel<<<grid, 256>>>(M, Oact, Nn,
        W0, X0, K0, ld0, ldW0,
        W1, X1, K1, ld1, ldW1,
        W2, X2, K2, ld2, ldW2,
        gInit, g0,
        nAcc, cntInv, sAcc, Y, epi, si, sj, iI, jI);
}

extern "C" void kernel_launch(void* const* d_in, const int* in_sizes, int n_in,
                              void* d_out, int out_size)
{
    if (n_in < 13) return;
    const float* xn_in = (const float*)d_in[0];
    const float* xe_in = (const float*)d_in[1];
    const int*   iInd  = (const int*)d_in[2];
    const int*   jInd  = (const int*)d_in[3];
    const float* K1No  = (const float*)d_in[4];
    const float* K2No  = (const float*)d_in[5];
    const float* K1Eo  = (const float*)d_in[6];
    const float* K2Eo  = (const float*)d_in[7];
    const float* KNout = (const float*)d_in[8];
    const float* KE1   = (const float*)d_in[9];
    const float* KE2   = (const float*)d_in[10];
    const float* KN1   = (const float*)d_in[11];
    const float* KN2   = (const float*)d_in[12];

    int N = in_sizes[0] / 32;
    int E = in_sizes[1] / 32;

    float *t, *xn, *yAT, *si, *sj, *wEa, *wEb, *wNi, *wNj, *wNn, *wE2, *wN2;
    float *k1n, *k2n, *k1e, *k2e, *ko;
    double* acc;
    cudaGetSymbolAddress((void**)&t,   g_t);
    cudaGetSymbolAddress((void**)&xn,  g_xn);
    cudaGetSymbolAddress((void**)&yAT, g_yAT);
    cudaGetSymbolAddress((void**)&si,  g_si);
    cudaGetSymbolAddress((void**)&sj,  g_sj);
    cudaGetSymbolAddress((void**)&wEa, g_wEa);
    cudaGetSymbolAddress((void**)&wEb, g_wEb);
    cudaGetSymbolAddress((void**)&wNi, g_wNi);
    cudaGetSymbolAddress((void**)&wNj, g_wNj);
    cudaGetSymbolAddress((void**)&wNn, g_wNn);
    cudaGetSymbolAddress((void**)&wE2, g_wE2);
    cudaGetSymbolAddress((void**)&wN2, g_wN2);
    cudaGetSymbolAddress((void**)&k1n, g_k1n);
    cudaGetSymbolAddress((void**)&k2n, g_k2n);
    cudaGetSymbolAddress((void**)&k1e, g_k1e);
    cudaGetSymbolAddress((void**)&k2e, g_k2e);
    cudaGetSymbolAddress((void**)&ko,  g_ko);
    cudaGetSymbolAddress((void**)&acc, g_acc);

    float* out = (float*)d_out;
    float* xe  = out + (size_t)64 * N;

    cudaMemsetAsync(acc, 0, 20 * sizeof(double), 0);
    prep_kernelA<<<(4 * 128 * 256 + 255) / 256, 256>>>(KE1, KN1, KE2, KN2);
    prep_kernelB<<<(128 * 128 + 255) / 256, 256>>>(K1No, K2No, K1Eo, K2Eo, KNout);

    const float* NUL = nullptr;
    const int*   NIL = nullptr;

    // opening node
    mm_launch(1, N, 128, k1n, xn_in, 32, N, 128, NUL,0,0,0,0, NUL,0,0,0,0, NUL, NIL,
              nullptr, 0.0, acc + 0, t, 0, nullptr, nullptr, nullptr, nullptr, 0);
    mm_launch(1, N, 128, k2n, t, 128, N, 128, NUL,0,0,0,0, NUL,0,0,0,0, NUL, NIL,
              acc + 0, 1.0 / (128.0 * N), nullptr, xn, 0, nullptr, nullptr, nullptr, nullptr, 0);

    // opening edge
    mm_launch(1, E, 128, k1e, xe_in, 32, E, 128, NUL,0,0,0,0, NUL,0,0,0,0, NUL, NIL,
              nullptr, 0.0, acc + 2, t, 0, nullptr, nullptr, nullptr, nullptr, 0);
    mm_launch(1, E, 128, k2e, t, 128, E, 128, NUL,0,0,0,0, NUL,0,0,0,0, NUL, NIL,
              acc + 2, 1.0 / (128.0 * E), nullptr, xe, 0, nullptr, nullptr, nullptr, nullptr, 0);

    for (int l = 0; l < 4; l++) {
        double* accE = acc + 4 + 4 * l;
        double* accN = acc + 6 + 4 * l;
        size_t ws = (size_t)l * 32768;

        // yAT = (wEa @ xn)^T, node-major [n][256]
        mm_launch(2, N, 256, wEa + ws, xn, 128, N, 256, NUL,0,0,0,0, NUL,0,0,0,0, NUL, NIL,
                  nullptr, 0.0, nullptr, yAT, 3, nullptr, nullptr, nullptr, nullptr, 0);

        // edge mm1': t[256,E] = gather(yAT, iInd) + wEb @ xe   (+stats)
        mm_launch(2, E, 256, wEb + ws, xe, 128, E, 256, NUL,0,0,0,0, NUL,0,0,0,0, yAT, iInd,
                  nullptr, 0.0, accE, t, 0, nullptr, nullptr, nullptr, nullptr, 0);

        cudaMemsetAsync(si, 0, (size_t)128 * N * sizeof(float), 0);
        cudaMemsetAsync(sj, 0, (size_t)128 * N * sizeof(float), 0);

        // edge mm2: xec = KE2 @ relu(norm(t)); xe += 0.1*xec; scatter -> si,sj
        mm_launch(1, E, 128, wE2 + ws, t, 256, E, 128, NUL,0,0,0,0, NUL,0,0,0,0, NUL, NIL,
                  accE, 1.0 / (256.0 * E), nullptr, xe, 2, si, sj, iInd, jInd, N);

        // node mm1: u[256,N] = Wi@si + Wj@sj + Wn@xn   (+stats)
        mm_launch(2, N, 256, wNi + ws, si, 128, N, 256,
                  wNj + ws, sj, 128, N, 256,
                  wNn + ws, xn, 128, N, 256, NUL, NIL,
                  nullptr, 0.0, accN, t, 0, nullptr, nullptr, nullptr, nullptr, 0);

        // node mm2: xn += 0.1 * (KN2 @ relu(norm(u)))
        mm_launch(1, N, 128, wN2 + ws, t, 256, N, 128, NUL,0,0,0,0, NUL,0,0,0,0, NUL, NIL,
                  accN, 1.0 / (256.0 * N), nullptr, xn, 1, nullptr, nullptr, nullptr, nullptr, 0);
    }

    // final: out[64,N] = KNout @ xn
    mm_launch(1, N, 64, ko, xn, 128, N, 128, NUL,0,0,0,0, NUL,0,0,0,0, NUL, NIL,
              nullptr, 0.0, nullptr, out, 0, nullptr, nullptr, nullptr, nullptr, 0);
}

// round 9
// speedup vs baseline: 1.2178x; 1.2178x over previous
#include <cuda_runtime.h>
#include <cuda_bf16.h>
#include <stdint.h>
#include <math.h>
#define NMAX 50000
#define EMAX 500000
typedef unsigned long long ull;
typedef unsigned int u32;

__device__ float g_t [(size_t)256*EMAX];
__device__ float g_xn [(size_t)128*NMAX];
__device__ float g_yAT[(size_t)256*NMAX];
__device__ float g_si [(size_t)128*NMAX];
__device__ float g_sj [(size_t)128*NMAX];
__device__ float g_wEa[4*128*256];
__device__ float g_wNi[4*128*256];
__device__ float g_wNj[4*128*256];
__device__ float g_wNn[4*128*256];
__device__ float g_wN2[4*256*128];
__device__ float g_k1n[32*128];
__device__ float g_k2n[128*128];
__device__ float g_k1e[32*128];
__device__ float g_ko [128*128];
__device__ __nv_bfloat16 g_bhE1[4*256*128], g_blE1[4*256*128];
__device__ __nv_bfloat16 g_bhE2[4*128*256], g_blE2[4*128*256];
__device__ __nv_bfloat16 g_bhOE[128*128],   g_blOE[128*128];
__device__ double g_acc[20];

__device__ __forceinline__ ull dup2(float v){ ull r; asm("mov.b64 %0,{%1,%1};":"=l"(r):"f"(v)); return r; }
__device__ __forceinline__ void ffma2(ull&d, ull a, ull b){ asm("fma.rn.f32x2 %0,%1,%2,%0;":"+l"(d):"l"(a),"l"(b)); }
__device__ __forceinline__ float2 f2of(ull u){ union{ull u; float2 f;} c; c.u=u; return c.f; }
__device__ __forceinline__ u32 smem_u32(const void*p){ u32 a; asm("{.reg .u64 t; cvta.to.shared.u64 t,%1; cvt.u32.u64 %0,t;}":"=r"(a):"l"(p)); return a; }
#define LDM4(r,a) asm volatile("ldmatrix.sync.aligned.m8n8.x4.shared.b16 {%0,%1,%2,%3},[%4];" \
    :"=r"((r)[0]),"=r"((r)[1]),"=r"((r)[2]),"=r"((r)[3]):"r"(a))
#define MMA(dd,a,b0,b1) asm volatile("mma.sync.aligned.m16n8k16.row.col.f32.bf16.bf16.f32 " \
    "{%0,%1,%2,%3},{%4,%5,%6,%7},{%8,%9},{%0,%1,%2,%3};" \
    :"+f"((dd)[0]),"+f"((dd)[1]),"+f"((dd)[2]),"+f"((dd)[3]) \
    :"r"((a)[0]),"r"((a)[1]),"r"((a)[2]),"r"((a)[3]),"r"(b0),"r"(b1))

__global__ void prep_kernelA(const float* __restrict__ KE1, const float* __restrict__ KN1,
                             const float* __restrict__ KE2, const float* __restrict__ KN2)
{
    int idx = blockIdx.x*blockDim.x + threadIdx.x;
    if (idx >= 4*128*256) return;
    int l = idx>>15, r = idx&32767;
    {
        int o = r&255, k = r>>8;
        size_t src = ((size_t)l*256 + o)*384;
        int dT = (l<<15) + k*256 + o;
        const float* e = KE1+src; const float* n = KN1+src;
        g_wEa[dT] = e[k] + e[128+k];
        float a = n[k], b = n[128+k];
        g_wNi[dT] = 0.5f*a + b; g_wNj[dT] = 0.5f*a - b; g_wNn[dT] = n[256+k];
        float w = e[256+k];
        __nv_bfloat16 h = __float2bfloat16(w);
        int dO = (l<<15) + o*128 + k;
        g_bhE1[dO] = h; g_blE1[dO] = __float2bfloat16(w - __bfloat162float(h));
    }
    {
        int o = r&127, k = r>>7;
        float w = KE2[((size_t)l*128 + o)*256 + k];
        __nv_bfloat16 h = __float2bfloat16(w);
        int dO = (l<<15) + o*256 + k;
        g_bhE2[dO] = h; g_blE2[dO] = __float2bfloat16(w - __bfloat162float(h));
        g_wN2[(l<<15) + k*128 + o] = KN2[((size_t)l*128 + o)*256 + k];
    }
}
__global__ void prep_kernelB(const float* __restrict__ K1No, const float* __restrict__ K2No,
                             const float* __restrict__ K1Eo, const float* __restrict__ K2Eo,
                             const float* __restrict__ KNout)
{
    int idx = blockIdx.x*blockDim.x + threadIdx.x;
    if (idx >= 128*128) return;
    int o = idx&127, k = idx>>7;
    if (k < 32) { g_k1n[k*128+o] = K1No[o*32+k]; g_k1e[k*128+o] = K1Eo[o*32+k]; }
    g_k2n[k*128+o] = K2No[o*128+k];
    g_ko [k*128+o] = (o<64) ? KNout[o*128+k] : 0.f;
    float w = K2Eo[o*128+k];
    __nv_bfloat16 h = __float2bfloat16(w);
    g_bhOE[o*128+k] = h; g_blOE[o*128+k] = __float2bfloat16(w - __bfloat162float(h));
}

// ---------- HMMA edge GEMM: D[128 edges, 128 outs/CTA.y] via bf16 3-split ----------
// epi 0: Y = D (+gInit gather) (+stats); epi 2: Y += 0.1D, scatter D to si/sj.
__global__ void __launch_bounds__(256, 2)
hmma_kernel(int E, int Nn, int K,
            const __nv_bfloat16* __restrict__ Whi, const __nv_bfloat16* __restrict__ Wlo,
            const float* __restrict__ X,
            const float* __restrict__ gInit, const int* __restrict__ g0,
            const double* __restrict__ normAcc, double cntInv, double* __restrict__ statAcc,
            float* __restrict__ Y, int epi,
            float* __restrict__ si, float* __restrict__ sj,
            const int* __restrict__ iI, const int* __restrict__ jI)
{
    __shared__ __align__(16) char smem[43008];   // Ah,Al,Bh,Bl @ 128x(32+8)bf16 each + 2KB red
    const int A_H = 0, A_L = 10240, B_H = 20480, B_L = 30720;
    const u32 sb = smem_u32(smem);

    const int tid = threadIdx.x, warp = tid>>5, lane = tid&31;
    const int m0 = blockIdx.x*128;
    const int oB = blockIdx.y*128;
    const int wm = warp>>1, wn = warp&1;
    const int ce = tid & 127, cg = tid >> 7;
    const bool cev = (m0 + ce) < E;

    const __nv_bfloat16* WhB = Whi + (size_t)oB*K;
    const __nv_bfloat16* WlB = Wlo + (size_t)oB*K;

    float mean = 0.f, inv = 0.f;
    const bool dn = (normAcc != nullptr);
    if (dn) {
        double mu = normAcc[0]*cntInv, va = normAcc[1]*cntInv - mu*mu;
        mean = (float)mu; inv = (float)rsqrt(va + 1e-5);
    }

    float d[2][8][4];
    #pragma unroll
    for (int a = 0; a < 2; a++)
        #pragma unroll
        for (int b = 0; b < 8; b++)
            #pragma unroll
            for (int c = 0; c < 4; c++) d[a][b][c] = 0.f;

    const int C = K >> 5;
    for (int c = 0; c < C; c++) {
        const int k0 = c*32;
        __syncthreads();
        // stage X (fp32 -> bf16 hi/lo, optional norm+relu)
        #pragma unroll
        for (int h = 0; h < 2; h++) {
            int kof = h*16 + cg*8;
            union { __nv_bfloat16 b[8]; uint4 u; } ph, pl;
            #pragma unroll
            for (int i = 0; i < 8; i++) {
                float x = cev ? X[(size_t)(k0+kof+i)*E + m0 + ce] : 0.f;
                if (dn) x = fmaxf((x - mean)*inv, 0.f);
                __nv_bfloat16 hb = __float2bfloat16(x);
                ph.b[i] = hb; pl.b[i] = __float2bfloat16(x - __bfloat162float(hb));
            }
            *(uint4*)(smem + A_H + ce*80 + kof*2) = ph.u;
            *(uint4*)(smem + A_L + ce*80 + kof*2) = pl.u;
        }
        // stage W (pre-split bf16)
        #pragma unroll
        for (int h = 0; h < 2; h++) {
            int kof = (cg + h*2)*8;
            *(uint4*)(smem + B_H + ce*80 + kof*2) = *(const uint4*)(WhB + (size_t)ce*K + k0 + kof);
            *(uint4*)(smem + B_L + ce*80 + kof*2) = *(const uint4*)(WlB + (size_t)ce*K + k0 + kof);
        }
        __syncthreads();
        // compute: 2 k16 steps
        #pragma unroll
        for (int kk = 0; kk < 32; kk += 16) {
            u32 ah[2][4], al[2][4];
            #pragma unroll
            for (int mt = 0; mt < 2; mt++) {
                u32 ra = sb + (u32)((wm*32 + mt*16 + (lane&15))*80 + (kk + ((lane>>4)<<3))*2);
                LDM4(ah[mt], A_H + ra);
                LDM4(al[mt], A_L + ra);
            }
            #pragma unroll
            for (int np = 0; np < 4; np++) {
                u32 rb = sb + (u32)((wn*64 + np*16 + (lane&7) + ((lane>>4)<<3))*80 + (kk + ((lane>>3)&1)*8)*2);
                u32 bh[4], bl[4];
                LDM4(bh, B_H + rb);
                LDM4(bl, B_L + rb);
                #pragma unroll
                for (int mt = 0; mt < 2; mt++) {
                    MMA(d[mt][np*2],   ah[mt], bh[0], bh[1]);
                    MMA(d[mt][np*2],   ah[mt], bl[0], bl[1]);
                    MMA(d[mt][np*2],   al[mt], bh[0], bh[1]);
                    MMA(d[mt][np*2+1], ah[mt], bh[2], bh[3]);
                    MMA(d[mt][np*2+1], ah[mt], bl[2], bl[3]);
                    MMA(d[mt][np*2+1], al[mt], bh[2], bh[3]);
                }
            }
        }
    }

    // ---- epilogue ----
    const int quad = lane>>2, tc = (lane&3)*2;
    float s = 0.f, q = 0.f;
    #pragma unroll
    for (int mt = 0; mt < 2; mt++) {
        #pragma unroll
        for (int hf = 0; hf < 2; hf++) {
            int e = m0 + wm*32 + mt*16 + quad + hf*8;
            if (e >= E) continue;
            const float* gp = nullptr;
            if (gInit) gp = gInit + (size_t)g0[e]*256;
            int ni = 0, nj = 0;
            if (epi == 2) { ni = iI[e]; nj = jI[e]; }
            #pragma unroll
            for (int nt = 0; nt < 8; nt++) {
                int o = oB + wn*64 + nt*8 + tc;
                float x0 = d[mt][nt][hf*2+0];
                float x1 = d[mt][nt][hf*2+1];
                if (gp) { x0 += gp[o - oB + oB]; x1 += gp[o + 1]; }
                if (epi == 0) {
                    Y[(size_t)o*E + e]     = x0;
                    Y[(size_t)(o+1)*E + e] = x1;
                    s += x0 + x1; q += x0*x0 + x1*x1;
                } else {
                    Y[(size_t)o*E + e]     += 0.1f*x0;
                    Y[(size_t)(o+1)*E + e] += 0.1f*x1;
                    atomicAdd(si + (size_t)o*Nn + ni, x0);
                    atomicAdd(si + (size_t)(o+1)*Nn + ni, x1);
                    atomicAdd(sj + (size_t)o*Nn + nj, x0);
                    atomicAdd(sj + (size_t)(o+1)*Nn + nj, x1);
                }
            }
        }
    }
    if (statAcc) {
        float* rs = (float*)(smem + 40960); float* rq = rs + 256;
        __syncthreads();
        rs[tid] = s; rq[tid] = q;
        __syncthreads();
        for (int st = 128; st > 0; st >>= 1) {
            if (tid < st) { rs[tid] += rs[tid+st]; rq[tid] += rq[tid+st]; }
            __syncthreads();
        }
        if (tid == 0) { atomicAdd(statAcc, (double)rs[0]); atomicAdd(statAcc+1, (double)rq[0]); }
    }
}

// ---------- SIMT f32x2 GEMM (node side) ----------
__global__ void __launch_bounds__(256, 2)
mm4_kernel(int M, int Oact,
           const float* __restrict__ W0, const float* __restrict__ X0, int K0, int ld0, int ldW0,
           const float* __restrict__ W1, const float* __restrict__ X1, int K1, int ld1, int ldW1,
           const float* __restrict__ W2, const float* __restrict__ X2, int K2, int ld2, int ldW2,
           const double* __restrict__ normAcc, double cntInv, double* __restrict__ statAcc,
           float* __restrict__ Y, int epi)
{
    __shared__ __align__(16) ull   Wd[2][8][132];
    __shared__ __align__(16) float Xs[2][8][132];
    const int tid = threadIdx.x, m0 = blockIdx.x*128, wb = blockIdx.y*128;
    const int lane = tid&31, warp = tid>>5;
    const int rbase = (warp>>2)*64 + (lane>>2)*4;
    const int cbase = (warp&3)*32 + (lane&3)*4;
    const int kkS = tid>>5, mfS = (tid&31)*4;

    float mean = 0.f, inv = 0.f;
    const bool dn = (normAcc != nullptr);
    if (dn) {
        double mu = normAcc[0]*cntInv, va = normAcc[1]*cntInv - mu*mu;
        mean = (float)mu; inv = (float)rsqrt(va + 1e-5);
    }
    ull acc[8][4];
    #pragma unroll
    for (int r = 0; r < 8; r++) { acc[r][0]=acc[r][1]=acc[r][2]=acc[r][3]=0ull; }

    const int c0 = K0>>3, c1 = W1 ? (K1>>3) : 0, c2 = W2 ? (K2>>3) : 0;
    const int totT = c0 + c1 + c2;
    auto ldg = [&](int t, float4& wv, float4& xv) {
        const float *W, *X; int ld, ldW, k0;
        if (t < c0)        { W=W0; X=X0; ld=ld0; ldW=ldW0; k0=t*8; }
        else if (t < c0+c1){ W=W1; X=X1; ld=ld1; ldW=ldW1; k0=(t-c0)*8; }
        else               { W=W2; X=X2; ld=ld2; ldW=ldW2; k0=(t-c0-c1)*8; }
        wv = *(const float4*)(W + (size_t)(k0+kkS)*ldW + wb + mfS);
        int m = m0 + mfS;
        if (m < M) {
            float4 v = *(const float4*)(X + (size_t)(k0+kkS)*ld + m);
            if (dn) {
                v.x = fmaxf((v.x-mean)*inv, 0.f); v.y = fmaxf((v.y-mean)*inv, 0.f);
                v.z = fmaxf((v.z-mean)*inv, 0.f); v.w = fmaxf((v.w-mean)*inv, 0.f);
            }
            xv = v;
        } else xv = make_float4(0.f,0.f,0.f,0.f);
    };
    auto sts = [&](int b, const float4& wv, const float4& xv) {
        ull* wr = &Wd[b][kkS][mfS];
        wr[0]=dup2(wv.x); wr[1]=dup2(wv.y); wr[2]=dup2(wv.z); wr[3]=dup2(wv.w);
        *(float4*)&Xs[b][kkS][mfS] = xv;
    };
    { float4 wv, xv; ldg(0, wv, xv); sts(0, wv, xv); }
    __syncthreads();
    float4 wpv, xpv;
    for (int t = 0; t < totT; t++) {
        const int cur = t&1; const bool more = (t+1 < totT);
        if (more) ldg(t+1, wpv, xpv);
        #pragma unroll
        for (int kk = 0; kk < 8; kk++) {
            ulonglong2 w01 = *(const ulonglong2*)&Wd[cur][kk][rbase];
            ulonglong2 w23 = *(const ulonglong2*)&Wd[cur][kk][rbase+2];
            ulonglong2 w45 = *(const ulonglong2*)&Wd[cur][kk][rbase+32];
            ulonglong2 w67 = *(const ulonglong2*)&Wd[cur][kk][rbase+34];
            ulonglong2 xa = *(const ulonglong2*)&Xs[cur][kk][cbase];
            ulonglong2 xb = *(const ulonglong2*)&Xs[cur][kk][cbase+16];
            ffma2(acc[0][0],w01.x,xa.x); ffma2(acc[0][1],w01.x,xa.y); ffma2(acc[0][2],w01.x,xb.x); ffma2(acc[0][3],w01.x,xb.y);
            ffma2(acc[1][0],w01.y,xa.x); ffma2(acc[1][1],w01.y,xa.y); ffma2(acc[1][2],w01.y,xb.x); ffma2(acc[1][3],w01.y,xb.y);
            ffma2(acc[2][0],w23.x,xa.x); ffma2(acc[2][1],w23.x,xa.y); ffma2(acc[2][2],w23.x,xb.x); ffma2(acc[2][3],w23.x,xb.y);
            ffma2(acc[3][0],w23.y,xa.x); ffma2(acc[3][1],w23.y,xa.y); ffma2(acc[3][2],w23.y,xb.x); ffma2(acc[3][3],w23.y,xb.y);
            ffma2(acc[4][0],w45.x,xa.x); ffma2(acc[4][1],w45.x,xa.y); ffma2(acc[4][2],w45.x,xb.x); ffma2(acc[4][3],w45.x,xb.y);
            ffma2(acc[5][0],w45.y,xa.x); ffma2(acc[5][1],w45.y,xa.y); ffma2(acc[5][2],w45.y,xb.x); ffma2(acc[5][3],w45.y,xb.y);
            ffma2(acc[6][0],w67.x,xa.x); ffma2(acc[6][1],w67.x,xa.y); ffma2(acc[6][2],w67.x,xb.x); ffma2(acc[6][3],w67.x,xb.y);
            ffma2(acc[7][0],w67.y,xa.x); ffma2(acc[7][1],w67.y,xa.y); ffma2(acc[7][2],w67.y,xb.x); ffma2(acc[7][3],w67.y,xb.y);
        }
        if (more) sts(cur^1, wpv, xpv);
        __syncthreads();
    }
    if (statAcc) {
        float s = 0.f, q = 0.f;
        #pragma unroll
        for (int r = 0; r < 8; r++)
            #pragma unroll
            for (int cg = 0; cg < 2; cg++)
                if (m0 + cbase + cg*16 < M) {
                    float2 a = f2of(acc[r][cg*2]), b = f2of(acc[r][cg*2+1]);
                    s += a.x+a.y+b.x+b.y; q += a.x*a.x+a.y*a.y+b.x*b.x+b.y*b.y;
                }
        __syncthreads();
        float* rs = (float*)Wd; float* rq = rs + 256;
        rs[tid] = s; rq[tid] = q;
        __syncthreads();
        for (int st = 128; st > 0; st >>= 1) {
            if (tid < st) { rs[tid] += rs[tid+st]; rq[tid] += rq[tid+st]; }
            __syncthreads();
        }
        if (tid == 0) { atomicAdd(statAcc,(double)rs[0]); atomicAdd(statAcc+1,(double)rq[0]); }
    }
    if (epi == 3) {
        #pragma unroll
        for (int j = 0; j < 4; j++)
            #pragma unroll
            for (int h = 0; h < 2; h++) {
                int c = m0 + cbase + (j>>1)*16 + (j&1)*2 + h;
                if (c >= M) continue;
                float4 v0, v1;
                if (h == 0) {
                    v0 = make_float4(f2of(acc[0][j]).x, f2of(acc[1][j]).x, f2of(acc[2][j]).x, f2of(acc[3][j]).x);
                    v1 = make_float4(f2of(acc[4][j]).x, f2of(acc[5][j]).x, f2of(acc[6][j]).x, f2of(acc[7][j]).x);
                } else {
                    v0 = make_float4(f2of(acc[0][j]).y, f2of(acc[1][j]).y, f2of(acc[2][j]).y, f2of(acc[3][j]).y);
                    v1 = make_float4(f2of(acc[4][j]).y, f2of(acc[5][j]).y, f2of(acc[6][j]).y, f2of(acc[7][j]).y);
                }
                float* dst = Y + (size_t)c*256 + wb + rbase;
                *(float4*)dst = v0; *(float4*)(dst+32) = v1;
            }
        return;
    }
    #pragma unroll
    for (int r = 0; r < 8; r++) {
        int o = wb + ((r < 4) ? (rbase + r) : (rbase + 28 + r));
        if (o >= Oact) continue;
        #pragma unroll
        for (int cg = 0; cg < 2; cg++) {
            int c = m0 + cbase + cg*16;
            if (c >= M) continue;
            float2 p0 = f2of(acc[r][cg*2]), p1 = f2of(acc[r][cg*2+1]);
            size_t off = (size_t)o*M + c;
            if (epi == 0) *(float4*)(Y+off) = make_float4(p0.x, p0.y, p1.x, p1.y);
            else {
                float4 old = *(float4*)(Y+off);
                old.x += 0.1f*p0.x; old.y += 0.1f*p0.y; old.z += 0.1f*p1.x; old.w += 0.1f*p1.y;
                *(float4*)(Y+off) = old;
            }
        }
    }
}

static inline void mm_launch(int gy, int M, int Oact,
    const float* W0, const float* X0, int K0, int ld0, int ldW0,
    const float* W1, const float* X1, int K1, int ld1, int ldW1,
    const float* W2, const float* X2, int K2, int ld2, int ldW2,
    const double* nA, double ci, double* sA, float* Y, int epi)
{
    dim3 g((M+127)/128, gy);
    mm4_kernel<<<g, 256>>>(M, Oact, W0,X0,K0,ld0,ldW0, W1,X1,K1,ld1,ldW1, W2,X2,K2,ld2,ldW2, nA, ci, sA, Y, epi);
}
static inline void hmma_launch(int E, int Nn, int O, int K,
    const __nv_bfloat16* Wh, const __nv_bfloat16* Wl, const float* X,
    const float* gI, const int* g0, const double* nA, double ci, double* sA,
    float* Y, int epi, float* si, float* sj, const int* iI, const int* jI)
{
    dim3 g((E+127)/128, O/128);
    hmma_kernel<<<g, 256>>>(E, Nn, K, Wh, Wl, X, gI, g0, nA, ci, sA, Y, epi, si, sj, iI, jI);
}

extern "C" void kernel_launch(void* const* d_in, const int* in_sizes, int n_in,
                              void* d_out, int out_size)
{
    if (n_in < 13) return;
    const float* xn_in = (const float*)d_in[0];
    const float* xe_in = (const float*)d_in[1];
    const int* iInd = (const int*)d_in[2];
    const int* jInd = (const int*)d_in[3];
    const float* K1No = (const float*)d_in[4];
    const float* K2No = (const float*)d_in[5];
    const float* K1Eo = (const float*)d_in[6];
    const float* K2Eo = (const float*)d_in[7];
    const float* KNout= (const float*)d_in[8];
    const float* KE1  = (const float*)d_in[9];
    const float* KE2  = (const float*)d_in[10];
    const float* KN1  = (const float*)d_in[11];
    const float* KN2  = (const float*)d_in[12];
    int N = in_sizes[0]/32, E = in_sizes[1]/32;

    float *t,*xn,*yAT,*si,*sj,*wEa,*wNi,*wNj,*wNn,*wN2,*k1n,*k2n,*k1e,*ko;
    __nv_bfloat16 *bhE1,*blE1,*bhE2,*blE2,*bhOE,*blOE;
    double* acc;
    cudaGetSymbolAddress((void**)&t,g_t);     cudaGetSymbolAddress((void**)&xn,g_xn);
    cudaGetSymbolAddress((void**)&yAT,g_yAT); cudaGetSymbolAddress((void**)&si,g_si);
    cudaGetSymbolAddress((void**)&sj,g_sj);   cudaGetSymbolAddress((void**)&wEa,g_wEa);
    cudaGetSymbolAddress((void**)&wNi,g_wNi); cudaGetSymbolAddress((void**)&wNj,g_wNj);
    cudaGetSymbolAddress((void**)&wNn,g_wNn); cudaGetSymbolAddress((void**)&wN2,g_wN2);
    cudaGetSymbolAddress((void**)&k1n,g_k1n); cudaGetSymbolAddress((void**)&k2n,g_k2n);
    cudaGetSymbolAddress((void**)&k1e,g_k1e); cudaGetSymbolAddress((void**)&ko,g_ko);
    cudaGetSymbolAddress((void**)&bhE1,g_bhE1); cudaGetSymbolAddress((void**)&blE1,g_blE1);
    cudaGetSymbolAddress((void**)&bhE2,g_bhE2); cudaGetSymbolAddress((void**)&blE2,g_blE2);
    cudaGetSymbolAddress((void**)&bhOE,g_bhOE); cudaGetSymbolAddress((void**)&blOE,g_blOE);
    cudaGetSymbolAddress((void**)&acc,g_acc);

    float* out = (float*)d_out;
    float* xe = out + (size_t)64*N;
    const float* NUL = nullptr;

    cudaMemsetAsync(acc, 0, 20*sizeof(double), 0);
    prep_kernelA<<<(4*128*256+255)/256, 256>>>(KE1, KN1, KE2, KN2);
    prep_kernelB<<<(128*128+255)/256, 256>>>(K1No, K2No, K1Eo, K2Eo, KNout);

    // opening node
    mm_launch(1, N, 128, k1n, xn_in, 32, N, 128, NUL,0,0,0,0, NUL,0,0,0,0, nullptr, 0.0, acc+0, t, 0);
    mm_launch(1, N, 128, k2n, t, 128, N, 128, NUL,0,0,0,0, NUL,0,0,0,0, acc+0, 1.0/(128.0*N), nullptr, xn, 0);
    // opening edge
    mm_launch(1, E, 128, k1e, xe_in, 32, E, 128, NUL,0,0,0,0, NUL,0,0,0,0, nullptr, 0.0, acc+2, t, 0);
    hmma_launch(E, N, 128, 128, bhOE, blOE, t, nullptr, nullptr, acc+2, 1.0/(128.0*E), nullptr,
                xe, 0, nullptr, nullptr, nullptr, nullptr);

    for (int l = 0; l < 4; l++) {
        double* accE = acc + 4 + 4*l;
        double* accN = acc + 6 + 4*l;
        size_t ws = (size_t)l*32768;
        // yAT = (wEa @ xn)^T node-major
        mm_launch(2, N, 256, wEa+ws, xn, 128, N, 256, NUL,0,0,0,0, NUL,0,0,0,0, nullptr, 0.0, nullptr, yAT, 3);
        // edge mm1': t = gather(yAT,iInd) + wEb @ xe  (+stats)
        hmma_launch(E, N, 256, 128, bhE1+ws, blE1+ws, xe, yAT, iInd, nullptr, 0.0, accE,
                    t, 0, nullptr, nullptr, nullptr, nullptr);
        cudaMemsetAsync(si, 0, (size_t)128*N*sizeof(float), 0);
        cudaMemsetAsync(sj, 0, (size_t)128*N*sizeof(float), 0);
        // edge mm2: xec = KE2 @ relu(norm(t)); xe += 0.1*xec; scatter
        hmma_launch(E, N, 128, 256, bhE2+ws, blE2+ws, t, nullptr, nullptr, accE, 1.0/(256.0*E), nullptr,
                    xe, 2, si, sj, iInd, jInd);
        // node mm1
        mm_launch(2, N, 256, wNi+ws, si, 128, N, 256, wNj+ws, sj, 128, N, 256, wNn+ws, xn, 128, N, 256,
                  nullptr, 0.0, accN, t, 0);
        // node mm2
        mm_launch(1, N, 128, wN2+ws, t, 256, N, 128, NUL,0,0,0,0, NUL,0,0,0,0,
                  accN, 1.0/(256.0*N), nullptr, xn, 1);
    }
    // final
    mm_launch(1, N, 64, ko, xn, 128, N, 128, NUL,0,0,0,0, NUL,0,0,0,0, nullptr, 0.0, nullptr, out, 0);
}

// round 10
// speedup vs baseline: 1.3009x; 1.0683x over previous
#include <cuda_runtime.h>
#include <cuda_bf16.h>
#include <stdint.h>
#include <math.h>
#define NMAX 50000
#define EMAX 500000
typedef unsigned long long ull;
typedef unsigned int u32;

__device__ float g_t [(size_t)256*EMAX];      // edge-major [E][256] for edges; channel-major [256][N] for node phase
__device__ float g_xe[(size_t)128*EMAX];      // edge-major xe scratch [E][128]
__device__ float g_xn [(size_t)128*NMAX];
__device__ float g_yAT[(size_t)256*NMAX];
__device__ float g_si [(size_t)128*NMAX];
__device__ float g_sj [(size_t)128*NMAX];
__device__ float g_wEa[4*128*256];
__device__ float g_wNi[4*128*256];
__device__ float g_wNj[4*128*256];
__device__ float g_wNn[4*128*256];
__device__ float g_wN2[4*256*128];
__device__ float g_k1n[32*128];
__device__ float g_k2n[128*128];
__device__ float g_k1e[32*128];
__device__ float g_ko [128*128];
__device__ __nv_bfloat16 g_bhE1[4*256*128], g_blE1[4*256*128];
__device__ __nv_bfloat16 g_bhE2[4*128*256], g_blE2[4*128*256];
__device__ __nv_bfloat16 g_bhOE[128*128],   g_blOE[128*128];
__device__ double g_acc[20];

__device__ __forceinline__ ull dup2(float v){ ull r; asm("mov.b64 %0,{%1,%1};":"=l"(r):"f"(v)); return r; }
__device__ __forceinline__ void ffma2(ull&d, ull a, ull b){ asm("fma.rn.f32x2 %0,%1,%2,%0;":"+l"(d):"l"(a),"l"(b)); }
__device__ __forceinline__ float2 f2of(ull u){ union{ull u; float2 f;} c; c.u=u; return c.f; }
__device__ __forceinline__ u32 smem_u32(const void*p){ u32 a; asm("{.reg .u64 t; cvta.to.shared.u64 t,%1; cvt.u32.u64 %0,t;}":"=r"(a):"l"(p)); return a; }
#define LDM4(r,a) asm volatile("ldmatrix.sync.aligned.m8n8.x4.shared.b16 {%0,%1,%2,%3},[%4];" \
    :"=r"((r)[0]),"=r"((r)[1]),"=r"((r)[2]),"=r"((r)[3]):"r"(a))
#define MMA(dd,a,b0,b1) asm volatile("mma.sync.aligned.m16n8k16.row.col.f32.bf16.bf16.f32 " \
    "{%0,%1,%2,%3},{%4,%5,%6,%7},{%8,%9},{%0,%1,%2,%3};" \
    :"+f"((dd)[0]),"+f"((dd)[1]),"+f"((dd)[2]),"+f"((dd)[3]) \
    :"r"((a)[0]),"r"((a)[1]),"r"((a)[2]),"r"((a)[3]),"r"(b0),"r"(b1))

__global__ void prep_kernelA(const float* __restrict__ KE1, const float* __restrict__ KN1,
                             const float* __restrict__ KE2, const float* __restrict__ KN2)
{
    int idx = blockIdx.x*blockDim.x + threadIdx.x;
    if (idx >= 4*128*256) return;
    int l = idx>>15, r = idx&32767;
    {
        int o = r&255, k = r>>8;
        size_t src = ((size_t)l*256 + o)*384;
        int dT = (l<<15) + k*256 + o;
        const float* e = KE1+src; const float* n = KN1+src;
        g_wEa[dT] = e[k] + e[128+k];
        float a = n[k], b = n[128+k];
        g_wNi[dT] = 0.5f*a + b; g_wNj[dT] = 0.5f*a - b; g_wNn[dT] = n[256+k];
        float w = e[256+k];
        __nv_bfloat16 h = __float2bfloat16(w);
        int dO = (l<<15) + o*128 + k;
        g_bhE1[dO] = h; g_blE1[dO] = __float2bfloat16(w - __bfloat162float(h));
    }
    {
        int o = r&127, k = r>>7;
        float w = KE2[((size_t)l*128 + o)*256 + k];
        __nv_bfloat16 h = __float2bfloat16(w);
        int dO = (l<<15) + o*256 + k;
        g_bhE2[dO] = h; g_blE2[dO] = __float2bfloat16(w - __bfloat162float(h));
        g_wN2[(l<<15) + k*128 + o] = KN2[((size_t)l*128 + o)*256 + k];
    }
}
__global__ void prep_kernelB(const float* __restrict__ K1No, const float* __restrict__ K2No,
                             const float* __restrict__ K1Eo, const float* __restrict__ K2Eo,
                             const float* __restrict__ KNout)
{
    int idx = blockIdx.x*blockDim.x + threadIdx.x;
    if (idx >= 128*128) return;
    int o = idx&127, k = idx>>7;
    if (k < 32) { g_k1n[k*128+o] = K1No[o*32+k]; g_k1e[k*128+o] = K1Eo[o*32+k]; }
    g_k2n[k*128+o] = K2No[o*128+k];
    g_ko [k*128+o] = (o<64) ? KNout[o*128+k] : 0.f;
    float w = K2Eo[o*128+k];
    __nv_bfloat16 h = __float2bfloat16(w);
    g_bhOE[o*128+k] = h; g_blOE[o*128+k] = __float2bfloat16(w - __bfloat162float(h));
}

// edge-major [E][128] -> channel-major [128][E]
__global__ void transposeEC(const float* __restrict__ src, float* __restrict__ dst, int E)
{
    __shared__ float tl[32][33];
    int e0 = blockIdx.x*32, c0 = blockIdx.y*32;
    int tx = threadIdx.x, ty = threadIdx.y;   // 32 x 8
    #pragma unroll
    for (int i = 0; i < 32; i += 8) {
        int e = e0 + ty + i;
        tl[ty+i][tx] = (e < E) ? src[(size_t)e*128 + c0 + tx] : 0.f;
    }
    __syncthreads();
    #pragma unroll
    for (int i = 0; i < 32; i += 8) {
        int e = e0 + tx;
        if (e < E) dst[(size_t)(c0 + ty + i)*E + e] = tl[tx][ty+i];
    }
}

// ---------- HMMA edge GEMM (X and Y edge-major): D[128e, 128o/CTA.y] via bf16 3-split ----------
__global__ void __launch_bounds__(256, 2)
hmma_kernel(int E, int Nn, int K, int ldX, int ldY,
            const __nv_bfloat16* __restrict__ Whi, const __nv_bfloat16* __restrict__ Wlo,
            const float* __restrict__ X,
            const float* __restrict__ gInit, const int* __restrict__ g0,
            const double* __restrict__ normAcc, double cntInv, double* __restrict__ statAcc,
            float* __restrict__ Y, int epi,
            float* __restrict__ si, float* __restrict__ sj,
            const int* __restrict__ iI, const int* __restrict__ jI)
{
    __shared__ __align__(16) char smem[43008];
    const int A_H = 0, A_L = 10240, B_H = 20480, B_L = 30720;
    const u32 sb = smem_u32(smem);

    const int tid = threadIdx.x, warp = tid>>5, lane = tid&31;
    const int m0 = blockIdx.x*128;
    const int oB = blockIdx.y*128;
    const int wm = warp>>1, wn = warp&1;
    const int ce = tid & 127, cg = tid >> 7;
    const bool cev = (m0 + ce) < E;

    const __nv_bfloat16* WhB = Whi + (size_t)oB*K;
    const __nv_bfloat16* WlB = Wlo + (size_t)oB*K;

    float mean = 0.f, inv = 0.f;
    const bool dn = (normAcc != nullptr);
    if (dn) {
        double mu = normAcc[0]*cntInv, va = normAcc[1]*cntInv - mu*mu;
        mean = (float)mu; inv = (float)rsqrt(va + 1e-5);
    }

    float d[2][8][4];
    #pragma unroll
    for (int a = 0; a < 2; a++)
        #pragma unroll
        for (int b = 0; b < 8; b++)
            #pragma unroll
            for (int c = 0; c < 4; c++) d[a][b][c] = 0.f;

    const float* xrow = X + (size_t)(m0 + ce)*ldX + cg*16;

    const int C = K >> 5;
    for (int c = 0; c < C; c++) {
        const int k0 = c*32;
        __syncthreads();
        // stage X: edge-major, 16 contiguous floats per thread (two 8-groups)
        #pragma unroll
        for (int h = 0; h < 2; h++) {
            float xv[8];
            if (cev) {
                float4 a4 = *(const float4*)(xrow + k0 + h*8);
                float4 b4 = *(const float4*)(xrow + k0 + h*8 + 4);
                xv[0]=a4.x; xv[1]=a4.y; xv[2]=a4.z; xv[3]=a4.w;
                xv[4]=b4.x; xv[5]=b4.y; xv[6]=b4.z; xv[7]=b4.w;
            } else {
                #pragma unroll
                for (int i = 0; i < 8; i++) xv[i] = 0.f;
            }
            union { __nv_bfloat16 b[8]; uint4 u; } ph, pl;
            #pragma unroll
            for (int i = 0; i < 8; i++) {
                float x = xv[i];
                if (dn) x = fmaxf((x - mean)*inv, 0.f);
                __nv_bfloat16 hb = __float2bfloat16(x);
                ph.b[i] = hb; pl.b[i] = __float2bfloat16(x - __bfloat162float(hb));
            }
            int kof = cg*16 + h*8;
            *(uint4*)(smem + A_H + ce*80 + kof*2) = ph.u;
            *(uint4*)(smem + A_L + ce*80 + kof*2) = pl.u;
        }
        // stage W (pre-split bf16, o-major k-contiguous)
        #pragma unroll
        for (int h = 0; h < 2; h++) {
            int kof = (cg + h*2)*8;
            *(uint4*)(smem + B_H + ce*80 + kof*2) = *(const uint4*)(WhB + (size_t)ce*K + k0 + kof);
            *(uint4*)(smem + B_L + ce*80 + kof*2) = *(const uint4*)(WlB + (size_t)ce*K + k0 + kof);
        }
        __syncthreads();
        #pragma unroll
        for (int kk = 0; kk < 32; kk += 16) {
            u32 ah[2][4], al[2][4];
            #pragma unroll
            for (int mt = 0; mt < 2; mt++) {
                u32 ra = sb + (u32)((wm*32 + mt*16 + (lane&15))*80 + (kk + ((lane>>4)<<3))*2);
                LDM4(ah[mt], A_H + ra);
                LDM4(al[mt], A_L + ra);
            }
            #pragma unroll
            for (int np = 0; np < 4; np++) {
                u32 rb = sb + (u32)((wn*64 + np*16 + (lane&7) + ((lane>>4)<<3))*80 + (kk + ((lane>>3)&1)*8)*2);
                u32 bh[4], bl[4];
                LDM4(bh, B_H + rb);
                LDM4(bl, B_L + rb);
                #pragma unroll
                for (int mt = 0; mt < 2; mt++) {
                    MMA(d[mt][np*2],   ah[mt], bh[0], bh[1]);
                    MMA(d[mt][np*2],   ah[mt], bl[0], bl[1]);
                    MMA(d[mt][np*2],   al[mt], bh[0], bh[1]);
                    MMA(d[mt][np*2+1], ah[mt], bh[2], bh[3]);
                    MMA(d[mt][np*2+1], ah[mt], bl[2], bl[3]);
                    MMA(d[mt][np*2+1], al[mt], bh[2], bh[3]);
                }
            }
        }
    }

    // ---- epilogue (Y edge-major) ----
    const int quad = lane>>2, tc = (lane&3)*2;
    float s = 0.f, q = 0.f;
    #pragma unroll
    for (int mt = 0; mt < 2; mt++) {
        #pragma unroll
        for (int hf = 0; hf < 2; hf++) {
            int e = m0 + wm*32 + mt*16 + quad + hf*8;
            if (e >= E) continue;
            const float* gp = nullptr;
            if (gInit) gp = gInit + (size_t)g0[e]*256;
            int ni = 0, nj = 0;
            if (epi == 2) { ni = iI[e]; nj = jI[e]; }
            float* yrow = Y + (size_t)e*ldY + oB;
            #pragma unroll
            for (int nt = 0; nt < 8; nt++) {
                int oL = wn*64 + nt*8 + tc;
                int o = oB + oL;
                float x0 = d[mt][nt][hf*2+0];
                float x1 = d[mt][nt][hf*2+1];
                if (gp) { x0 += gp[o]; x1 += gp[o+1]; }
                if (epi == 0) {
                    *(float2*)(yrow + oL) = make_float2(x0, x1);
                    s += x0 + x1; q += x0*x0 + x1*x1;
                } else {
                    float2 old = *(float2*)(yrow + oL);
                    old.x += 0.1f*x0; old.y += 0.1f*x1;
                    *(float2*)(yrow + oL) = old;
                    atomicAdd(si + (size_t)o*Nn + ni, x0);
                    atomicAdd(si + (size_t)(o+1)*Nn + ni, x1);
                    atomicAdd(sj + (size_t)o*Nn + nj, x0);
                    atomicAdd(sj + (size_t)(o+1)*Nn + nj, x1);
                }
            }
        }
    }
    if (statAcc) {
        float* rs = (float*)(smem + 40960); float* rq = rs + 256;
        __syncthreads();
        rs[tid] = s; rq[tid] = q;
        __syncthreads();
        for (int st = 128; st > 0; st >>= 1) {
            if (tid < st) { rs[tid] += rs[tid+st]; rq[tid] += rq[tid+st]; }
            __syncthreads();
        }
        if (tid == 0) { atomicAdd(statAcc, (double)rs[0]); atomicAdd(statAcc+1, (double)rq[0]); }
    }
}

// ---------- SIMT f32x2 GEMM (node side + producers of edge-major t) ----------
__global__ void __launch_bounds__(256, 2)
mm4_kernel(int M, int Oact, int ldY3,
           const float* __restrict__ W0, const float* __restrict__ X0, int K0, int ld0, int ldW0,
           const float* __restrict__ W1, const float* __restrict__ X1, int K1, int ld1, int ldW1,
           const float* __restrict__ W2, const float* __restrict__ X2, int K2, int ld2, int ldW2,
           const double* __restrict__ normAcc, double cntInv, double* __restrict__ statAcc,
           float* __restrict__ Y, int epi)
{
    __shared__ __align__(16) ull   Wd[2][8][132];
    __shared__ __align__(16) float Xs[2][8][132];
    const int tid = threadIdx.x, m0 = blockIdx.x*128, wb = blockIdx.y*128;
    const int lane = tid&31, warp = tid>>5;
    const int rbase = (warp>>2)*64 + (lane>>2)*4;
    const int cbase = (warp&3)*32 + (lane&3)*4;
    const int kkS = tid>>5, mfS = (tid&31)*4;

    float mean = 0.f, inv = 0.f;
    const bool dn = (normAcc != nullptr);
    if (dn) {
        double mu = normAcc[0]*cntInv, va = normAcc[1]*cntInv - mu*mu;
        mean = (float)mu; inv = (float)rsqrt(va + 1e-5);
    }
    ull acc[8][4];
    #pragma unroll
    for (int r = 0; r < 8; r++) { acc[r][0]=acc[r][1]=acc[r][2]=acc[r][3]=0ull; }

    const int c0 = K0>>3, c1 = W1 ? (K1>>3) : 0, c2 = W2 ? (K2>>3) : 0;
    const int totT = c0 + c1 + c2;
    auto ldg = [&](int t, float4& wv, float4& xv) {
        const float *W, *X; int ld, ldW, k0;
        if (t < c0)        { W=W0; X=X0; ld=ld0; ldW=ldW0; k0=t*8; }
        else if (t < c0+c1){ W=W1; X=X1; ld=ld1; ldW=ldW1; k0=(t-c0)*8; }
        else               { W=W2; X=X2; ld=ld2; ldW=ldW2; k0=(t-c0-c1)*8; }
        wv = *(const float4*)(W + (size_t)(k0+kkS)*ldW + wb + mfS);
        int m = m0 + mfS;
        if (m < M) {
            float4 v = *(const float4*)(X + (size_t)(k0+kkS)*ld + m);
            if (dn) {
                v.x = fmaxf((v.x-mean)*inv, 0.f); v.y = fmaxf((v.y-mean)*inv, 0.f);
                v.z = fmaxf((v.z-mean)*inv, 0.f); v.w = fmaxf((v.w-mean)*inv, 0.f);
            }
            xv = v;
        } else xv = make_float4(0.f,0.f,0.f,0.f);
    };
    auto sts = [&](int b, const float4& wv, const float4& xv) {
        ull* wr = &Wd[b][kkS][mfS];
        wr[0]=dup2(wv.x); wr[1]=dup2(wv.y); wr[2]=dup2(wv.z); wr[3]=dup2(wv.w);
        *(float4*)&Xs[b][kkS][mfS] = xv;
    };
    { float4 wv, xv; ldg(0, wv, xv); sts(0, wv, xv); }
    __syncthreads();
    float4 wpv, xpv;
    for (int t = 0; t < totT; t++) {
        const int cur = t&1; const bool more = (t+1 < totT);
        if (more) ldg(t+1, wpv, xpv);
        #pragma unroll
        for (int kk = 0; kk < 8; kk++) {
            ulonglong2 w01 = *(const ulonglong2*)&Wd[cur][kk][rbase];
            ulonglong2 w23 = *(const ulonglong2*)&Wd[cur][kk][rbase+2];
            ulonglong2 w45 = *(const ulonglong2*)&Wd[cur][kk][rbase+32];
            ulonglong2 w67 = *(const ulonglong2*)&Wd[cur][kk][rbase+34];
            ulonglong2 xa = *(const ulonglong2*)&Xs[cur][kk][cbase];
            ulonglong2 xb = *(const ulonglong2*)&Xs[cur][kk][cbase+16];
            ffma2(acc[0][0],w01.x,xa.x); ffma2(acc[0][1],w01.x,xa.y); ffma2(acc[0][2],w01.x,xb.x); ffma2(acc[0][3],w01.x,xb.y);
            ffma2(acc[1][0],w01.y,xa.x); ffma2(acc[1][1],w01.y,xa.y); ffma2(acc[1][2],w01.y,xb.x); ffma2(acc[1][3],w01.y,xb.y);
            ffma2(acc[2][0],w23.x,xa.x); ffma2(acc[2][1],w23.x,xa.y); ffma2(acc[2][2],w23.x,xb.x); ffma2(acc[2][3],w23.x,xb.y);
            ffma2(acc[3][0],w23.y,xa.x); ffma2(acc[3][1],w23.y,xa.y); ffma2(acc[3][2],w23.y,xb.x); ffma2(acc[3][3],w23.y,xb.y);
            ffma2(acc[4][0],w45.x,xa.x); ffma2(acc[4][1],w45.x,xa.y); ffma2(acc[4][2],w45.x,xb.x); ffma2(acc[4][3],w45.x,xb.y);
            ffma2(acc[5][0],w45.y,xa.x); ffma2(acc[5][1],w45.y,xa.y); ffma2(acc[5][2],w45.y,xb.x); ffma2(acc[5][3],w45.y,xb.y);
            ffma2(acc[6][0],w67.x,xa.x); ffma2(acc[6][1],w67.x,xa.y); ffma2(acc[6][2],w67.x,xb.x); ffma2(acc[6][3],w67.x,xb.y);
            ffma2(acc[7][0],w67.y,xa.x); ffma2(acc[7][1],w67.y,xa.y); ffma2(acc[7][2],w67.y,xb.x); ffma2(acc[7][3],w67.y,xb.y);
        }
        if (more) sts(cur^1, wpv, xpv);
        __syncthreads();
    }
    if (statAcc) {
        float s = 0.f, q = 0.f;
        #pragma unroll
        for (int r = 0; r < 8; r++)
            #pragma unroll
            for (int cg = 0; cg < 2; cg++)
                if (m0 + cbase + cg*16 < M) {
                    float2 a = f2of(acc[r][cg*2]), b = f2of(acc[r][cg*2+1]);
                    s += a.x+a.y+b.x+b.y; q += a.x*a.x+a.y*a.y+b.x*b.x+b.y*b.y;
                }
        __syncthreads();
        float* rs = (float*)Wd; float* rq = rs + 256;
        rs[tid] = s; rq[tid] = q;
        __syncthreads();
        for (int st = 128; st > 0; st >>= 1) {
            if (tid < st) { rs[tid] += rs[tid+st]; rq[tid] += rq[tid+st]; }
            __syncthreads();
        }
        if (tid == 0) { atomicAdd(statAcc,(double)rs[0]); atomicAdd(statAcc+1,(double)rq[0]); }
    }
    if (epi == 3) {
        #pragma unroll
        for (int j = 0; j < 4; j++)
            #pragma unroll
            for (int h = 0; h < 2; h++) {
                int c = m0 + cbase + (j>>1)*16 + (j&1)*2 + h;
                if (c >= M) continue;
                float4 v0, v1;
                if (h == 0) {
                    v0 = make_float4(f2of(acc[0][j]).x, f2of(acc[1][j]).x, f2of(acc[2][j]).x, f2of(acc[3][j]).x);
                    v1 = make_float4(f2of(acc[4][j]).x, f2of(acc[5][j]).x, f2of(acc[6][j]).x, f2of(acc[7][j]).x);
                } else {
                    v0 = make_float4(f2of(acc[0][j]).y, f2of(acc[1][j]).y, f2of(acc[2][j]).y, f2of(acc[3][j]).y);
                    v1 = make_float4(f2of(acc[4][j]).y, f2of(acc[5][j]).y, f2of(acc[6][j]).y, f2of(acc[7][j]).y);
                }
                float* dst = Y + (size_t)c*ldY3 + wb + rbase;
                *(float4*)dst = v0; *(float4*)(dst+32) = v1;
            }
        return;
    }
    #pragma unroll
    for (int r = 0; r < 8; r++) {
        int o = wb + ((r < 4) ? (rbase + r) : (rbase + 28 + r));
        if (o >= Oact) continue;
        #pragma unroll
        for (int cg = 0; cg < 2; cg++) {
            int c = m0 + cbase + cg*16;
            if (c >= M) continue;
            float2 p0 = f2of(acc[r][cg*2]), p1 = f2of(acc[r][cg*2+1]);
            size_t off = (size_t)o*M + c;
            if (epi == 0) *(float4*)(Y+off) = make_float4(p0.x, p0.y, p1.x, p1.y);
            else {
                float4 old = *(float4*)(Y+off);
                old.x += 0.1f*p0.x; old.y += 0.1f*p0.y; old.z += 0.1f*p1.x; old.w += 0.1f*p1.y;
                *(float4*)(Y+off) = old;
            }
        }
    }
}

static inline void mm_launch(int gy, int M, int Oact, int ldY3,
    const float* W0, const float* X0, int K0, int ld0, int ldW0,
    const float* W1, const float* X1, int K1, int ld1, int ldW1,
    const float* W2, const float* X2, int K2, int ld2, int ldW2,
    const double* nA, double ci, double* sA, float* Y, int epi)
{
    dim3 g((M+127)/128, gy);
    mm4_kernel<<<g, 256>>>(M, Oact, ldY3, W0,X0,K0,ld0,ldW0, W1,X1,K1,ld1,ldW1, W2,X2,K2,ld2,ldW2, nA, ci, sA, Y, epi);
}
static inline void hmma_launch(int E, int Nn, int O, int K, int ldX, int ldY,
    const __nv_bfloat16* Wh, const __nv_bfloat16* Wl, const float* X,
    const float* gI, const int* g0, const double* nA, double ci, double* sA,
    float* Y, int epi, float* si, float* sj, const int* iI, const int* jI)
{
    dim3 g((E+127)/128, O/128);
    hmma_kernel<<<g, 256>>>(E, Nn, K, ldX, ldY, Wh, Wl, X, gI, g0, nA, ci, sA, Y, epi, si, sj, iI, jI);
}

extern "C" void kernel_launch(void* const* d_in, const int* in_sizes, int n_in,
                              void* d_out, int out_size)
{
    if (n_in < 13) return;
    const float* xn_in = (const float*)d_in[0];
    const float* xe_in = (const float*)d_in[1];
    const int* iInd = (const int*)d_in[2];
    const int* jInd = (const int*)d_in[3];
    const float* K1No = (const float*)d_in[4];
    const float* K2No = (const float*)d_in[5];
    const float* K1Eo = (const float*)d_in[6];
    const float* K2Eo = (const float*)d_in[7];
    const float* KNout= (const float*)d_in[8];
    const float* KE1  = (const float*)d_in[9];
    const float* KE2  = (const float*)d_in[10];
    const float* KN1  = (const float*)d_in[11];
    const float* KN2  = (const float*)d_in[12];
    int N = in_sizes[0]/32, E = in_sizes[1]/32;

    float *t,*xe,*xn,*yAT,*si,*sj,*wEa,*wNi,*wNj,*wNn,*wN2,*k1n,*k2n,*k1e,*ko;
    __nv_bfloat16 *bhE1,*blE1,*bhE2,*blE2,*bhOE,*blOE;
    double* acc;
    cudaGetSymbolAddress((void**)&t,g_t);     cudaGetSymbolAddress((void**)&xe,g_xe);
    cudaGetSymbolAddress((void**)&xn,g_xn);
    cudaGetSymbolAddress((void**)&yAT,g_yAT); cudaGetSymbolAddress((void**)&si,g_si);
    cudaGetSymbolAddress((void**)&sj,g_sj);   cudaGetSymbolAddress((void**)&wEa,g_wEa);
    cudaGetSymbolAddress((void**)&wNi,g_wNi); cudaGetSymbolAddress((void**)&wNj,g_wNj);
    cudaGetSymbolAddress((void**)&wNn,g_wNn); cudaGetSymbolAddress((void**)&wN2,g_wN2);
    cudaGetSymbolAddress((void**)&k1n,g_k1n); cudaGetSymbolAddress((void**)&k2n,g_k2n);
    cudaGetSymbolAddress((void**)&k1e,g_k1e); cudaGetSymbolAddress((void**)&ko,g_ko);
    cudaGetSymbolAddress((void**)&bhE1,g_bhE1); cudaGetSymbolAddress((void**)&blE1,g_blE1);
    cudaGetSymbolAddress((void**)&bhE2,g_bhE2); cudaGetSymbolAddress((void**)&blE2,g_blE2);
    cudaGetSymbolAddress((void**)&bhOE,g_bhOE); cudaGetSymbolAddress((void**)&blOE,g_blOE);
    cudaGetSymbolAddress((void**)&acc,g_acc);

    float* out = (float*)d_out;
    float* xe_out = out + (size_t)64*N;
    const float* NUL = nullptr;

    cudaMemsetAsync(acc, 0, 20*sizeof(double), 0);
    prep_kernelA<<<(4*128*256+255)/256, 256>>>(KE1, KN1, KE2, KN2);
    prep_kernelB<<<(128*128+255)/256, 256>>>(K1No, K2No, K1Eo, K2Eo, KNout);

    // opening node (channel-major throughout)
    mm_launch(1, N, 128, 0, k1n, xn_in, 32, N, 128, NUL,0,0,0,0, NUL,0,0,0,0, nullptr, 0.0, acc+0, t, 0);
    mm_launch(1, N, 128, 0, k2n, t, 128, N, 128, NUL,0,0,0,0, NUL,0,0,0,0, acc+0, 1.0/(128.0*N), nullptr, xn, 0);

    // opening edge: t_open edge-major [E][128] via epi3; then hmma -> xe scratch edge-major
    mm_launch(1, E, 128, 128, k1e, xe_in, 32, E, 128, NUL,0,0,0,0, NUL,0,0,0,0, nullptr, 0.0, acc+2, t, 3);
    hmma_launch(E, N, 128, 128, 128, 128, bhOE, blOE, t, nullptr, nullptr, acc+2, 1.0/(128.0*E), nullptr,
                xe, 0, nullptr, nullptr, nullptr, nullptr);

    for (int l = 0; l < 4; l++) {
        double* accE = acc + 4 + 4*l;
        double* accN = acc + 6 + 4*l;
        size_t ws = (size_t)l*32768;
        // yAT = (wEa @ xn)^T node-major [n][256]
        mm_launch(2, N, 256, 256, wEa+ws, xn, 128, N, 256, NUL,0,0,0,0, NUL,0,0,0,0, nullptr, 0.0, nullptr, yAT, 3);
        // edge mm1': t[e][256] = gather(yAT,iInd) + wEb @ xe   (+stats)
        hmma_launch(E, N, 256, 128, 128, 256, bhE1+ws, blE1+ws, xe, yAT, iInd, nullptr, 0.0, accE,
                    t, 0, nullptr, nullptr, nullptr, nullptr);
        cudaMemsetAsync(si, 0, (size_t)128*N*sizeof(float), 0);
        cudaMemsetAsync(sj, 0, (size_t)128*N*sizeof(float), 0);
        // edge mm2: xec = KE2 @ relu(norm(t)); xe += 0.1*xec; scatter
        hmma_launch(E, N, 128, 256, 256, 128, bhE2+ws, blE2+ws, t, nullptr, nullptr, accE, 1.0/(256.0*E), nullptr,
                    xe, 2, si, sj, iInd, jInd);
        // node mm1 (t reused channel-major [256][N])
        mm_launch(2, N, 256, 0, wNi+ws, si, 128, N, 256, wNj+ws, sj, 128, N, 256, wNn+ws, xn, 128, N, 256,
                  nullptr, 0.0, accN, t, 0);
        // node mm2
        mm_launch(1, N, 128, 0, wN2+ws, t, 256, N, 128, NUL,0,0,0,0, NUL,0,0,0,0,
                  accN, 1.0/(256.0*N), nullptr, xn, 1);
    }
    // final node out + xe transpose to channel-major output
    mm_launch(1, N, 64, 0, ko, xn, 128, N, 128, NUL,0,0,0,0, NUL,0,0,0,0, nullptr, 0.0, nullptr, out, 0);
    {
        dim3 tg((E+31)/32, 4), tb(32, 8);
        transposeEC<<<tg, tb>>>(xe, xe_out, E);
    }
}

// round 11
// speedup vs baseline: 1.6292x; 1.2524x over previous
#include <cuda_runtime.h>
#include <cuda_bf16.h>
#include <stdint.h>
#include <math.h>
#define NMAX 50000
#define EMAX 500000
typedef unsigned long long ull;
typedef unsigned int u32;

__device__ float g_t [(size_t)256*EMAX];      // edge phase: [E][256] edge-major; node phase: [n][256] node-major; open: [128][N] or [E][128]
__device__ float g_xe[(size_t)128*EMAX];      // edge-major xe scratch [E][128]
__device__ float g_sN[(size_t)384*NMAX];      // stacked node rows: [n][0:128)=si, [128:256)=sj, [256:384)=xn
__device__ float g_yAT[(size_t)256*NMAX];     // node-major [n][256]; also reused as final tmp [n][128]
__device__ float g_k1n[32*128];
__device__ float g_k2n[128*128];
__device__ float g_k1e[32*128];
// bf16 split weights, all [O][K] k-contiguous
__device__ __nv_bfloat16 g_bhN1[4*256*384], g_blN1[4*256*384];  // stacked (0.5a+b | 0.5a-b | c)
__device__ __nv_bfloat16 g_bhN2[4*128*256], g_blN2[4*128*256];
__device__ __nv_bfloat16 g_bhEa[4*256*128], g_blEa[4*256*128];  // wEa (for yAT)
__device__ __nv_bfloat16 g_bhE1[4*256*128], g_blE1[4*256*128];  // wEb (edge mm1')
__device__ __nv_bfloat16 g_bhE2[4*128*256], g_blE2[4*128*256];
__device__ __nv_bfloat16 g_bhOE[128*128],   g_blOE[128*128];
__device__ __nv_bfloat16 g_bhKO[128*128],   g_blKO[128*128];
__device__ double g_acc[20];

__device__ __forceinline__ ull dup2(float v){ ull r; asm("mov.b64 %0,{%1,%1};":"=l"(r):"f"(v)); return r; }
__device__ __forceinline__ void ffma2(ull&d, ull a, ull b){ asm("fma.rn.f32x2 %0,%1,%2,%0;":"+l"(d):"l"(a),"l"(b)); }
__device__ __forceinline__ float2 f2of(ull u){ union{ull u; float2 f;} c; c.u=u; return c.f; }
__device__ __forceinline__ u32 smem_u32(const void*p){ u32 a; asm("{.reg .u64 t; cvta.to.shared.u64 t,%1; cvt.u32.u64 %0,t;}":"=r"(a):"l"(p)); return a; }
#define LDM4(r,a) asm volatile("ldmatrix.sync.aligned.m8n8.x4.shared.b16 {%0,%1,%2,%3},[%4];" \
    :"=r"((r)[0]),"=r"((r)[1]),"=r"((r)[2]),"=r"((r)[3]):"r"(a))
#define MMA(dd,a,b0,b1) asm volatile("mma.sync.aligned.m16n8k16.row.col.f32.bf16.bf16.f32 " \
    "{%0,%1,%2,%3},{%4,%5,%6,%7},{%8,%9},{%0,%1,%2,%3};" \
    :"+f"((dd)[0]),"+f"((dd)[1]),"+f"((dd)[2]),"+f"((dd)[3]) \
    :"r"((a)[0]),"r"((a)[1]),"r"((a)[2]),"r"((a)[3]),"r"(b0),"r"(b1))
#define REDV2(p,x0,x1) asm volatile("red.global.add.v2.f32 [%0], {%1, %2};" :: "l"(p), "f"(x0), "f"(x1) : "memory")

__device__ __forceinline__ void bsplit(float w, __nv_bfloat16& h, __nv_bfloat16& l){
    h = __float2bfloat16(w); l = __float2bfloat16(w - __bfloat162float(h));
}

__global__ void prep_kernelA(const float* __restrict__ KE1, const float* __restrict__ KN1,
                             const float* __restrict__ KE2, const float* __restrict__ KN2)
{
    int idx = blockIdx.x*blockDim.x + threadIdx.x;
    if (idx >= 4*256*384) return;
    int l = idx / (256*384), r = idx % (256*384);
    int o = r / 384, k = r % 384;
    // N1 stacked
    {
        const float* n = KN1 + ((size_t)(l*256 + o))*384;
        int kk = k & 127, reg = k >> 7;
        float a = n[kk], b = n[128+kk];
        float w = (reg == 0) ? 0.5f*a + b : ((reg == 1) ? 0.5f*a - b : n[256+kk]);
        bsplit(w, g_bhN1[(size_t)(l*256+o)*384 + k], g_blN1[(size_t)(l*256+o)*384 + k]);
    }
    if (k < 128) {
        const float* e = KE1 + ((size_t)(l*256 + o))*384;
        int d = (l*256 + o)*128 + k;
        bsplit(e[k] + e[128+k], g_bhEa[d], g_blEa[d]);
        bsplit(e[256+k],        g_bhE1[d], g_blE1[d]);
    }
    if (o < 128 && k < 256) {
        int d = (l*128 + o)*256 + k;
        bsplit(KE2[(size_t)(l*128+o)*256 + k], g_bhE2[d], g_blE2[d]);
        bsplit(KN2[(size_t)(l*128+o)*256 + k], g_bhN2[d], g_blN2[d]);
    }
}
__global__ void prep_kernelB(const float* __restrict__ K1No, const float* __restrict__ K2No,
                             const float* __restrict__ K1Eo, const float* __restrict__ K2Eo,
                             const float* __restrict__ KNout)
{
    int idx = blockIdx.x*blockDim.x + threadIdx.x;
    if (idx >= 128*128) return;
    int o = idx&127, k = idx>>7;
    if (k < 32) { g_k1n[k*128+o] = K1No[o*32+k]; g_k1e[k*128+o] = K1Eo[o*32+k]; }
    g_k2n[k*128+o] = K2No[o*128+k];
    bsplit(K2Eo[o*128+k], g_bhOE[o*128+k], g_blOE[o*128+k]);
    bsplit((o < 64) ? KNout[o*128+k] : 0.f, g_bhKO[o*128+k], g_blKO[o*128+k]);
}

// zero si|sj regions of sN (first 256 floats of each 384-row)
__global__ void zeroS(float* s, int N)
{
    int i = blockIdx.x*blockDim.x + threadIdx.x;
    if (i >= N*64) return;
    int n = i >> 6, c = (i & 63)*4;
    *(float4*)(s + (size_t)n*384 + c) = make_float4(0.f,0.f,0.f,0.f);
}

// node/edge-major [m][ldS] -> channel-major [rows][M]
__global__ void transposeNC(const float* __restrict__ src, float* __restrict__ dst,
                            int M, int ldS, int rows)
{
    __shared__ float tl[32][33];
    int m0 = blockIdx.x*32, c0 = blockIdx.y*32;
    int tx = threadIdx.x, ty = threadIdx.y;   // 32 x 8
    #pragma unroll
    for (int i = 0; i < 32; i += 8) {
        int m = m0 + ty + i;
        tl[ty+i][tx] = (m < M) ? src[(size_t)m*ldS + c0 + tx] : 0.f;
    }
    __syncthreads();
    #pragma unroll
    for (int i = 0; i < 32; i += 8) {
        int m = m0 + tx, c = c0 + ty + i;
        if (m < M && c < rows) dst[(size_t)c*M + m] = tl[tx][ty+i];
    }
}

// ---------- HMMA GEMM (X,Y row-major per m): D[128m, 128o/CTA.y] via bf16 3-split ----------
// epi 0: Y=v (+gInit) (+stats);  epi 1: Y += 0.1v;  epi 2: Y += 0.1v AND red.v2 scatter to sc rows.
__global__ void __launch_bounds__(256, 2)
hmma_kernel(int E, int K, int ldX, int ldY,
            const __nv_bfloat16* __restrict__ Whi, const __nv_bfloat16* __restrict__ Wlo,
            const float* __restrict__ X,
            const float* __restrict__ gInit, const int* __restrict__ g0,
            const double* __restrict__ normAcc, double cntInv, double* __restrict__ statAcc,
            float* __restrict__ Y, int epi,
            float* __restrict__ sc, int ldS,
            const int* __restrict__ iI, const int* __restrict__ jI)
{
    __shared__ __align__(16) char smem[43008];
    const int A_H = 0, A_L = 10240, B_H = 20480, B_L = 30720;
    const u32 sb = smem_u32(smem);

    const int tid = threadIdx.x, warp = tid>>5, lane = tid&31;
    const int m0 = blockIdx.x*128;
    const int oB = blockIdx.y*128;
    const int wm = warp>>1, wn = warp&1;
    const int ce = tid & 127, cg = tid >> 7;
    const bool cev = (m0 + ce) < E;

    const __nv_bfloat16* WhB = Whi + (size_t)oB*K;
    const __nv_bfloat16* WlB = Wlo + (size_t)oB*K;

    float mean = 0.f, inv = 0.f;
    const bool dn = (normAcc != nullptr);
    if (dn) {
        double mu = normAcc[0]*cntInv, va = normAcc[1]*cntInv - mu*mu;
        mean = (float)mu; inv = (float)rsqrt(va + 1e-5);
    }

    float d[2][8][4];
    #pragma unroll
    for (int a = 0; a < 2; a++)
        #pragma unroll
        for (int b = 0; b < 8; b++)
            #pragma unroll
            for (int c = 0; c < 4; c++) d[a][b][c] = 0.f;

    const float* xrow = X + (size_t)(m0 + ce)*ldX + cg*16;

    const int C = K >> 5;
    for (int c = 0; c < C; c++) {
        const int k0 = c*32;
        __syncthreads();
        #pragma unroll
        for (int h = 0; h < 2; h++) {
            float xv[8];
            if (cev) {
                float4 a4 = *(const float4*)(xrow + k0 + h*8);
                float4 b4 = *(const float4*)(xrow + k0 + h*8 + 4);
                xv[0]=a4.x; xv[1]=a4.y; xv[2]=a4.z; xv[3]=a4.w;
                xv[4]=b4.x; xv[5]=b4.y; xv[6]=b4.z; xv[7]=b4.w;
            } else {
                #pragma unroll
                for (int i = 0; i < 8; i++) xv[i] = 0.f;
            }
            union { __nv_bfloat16 b[8]; uint4 u; } ph, pl;
            #pragma unroll
            for (int i = 0; i < 8; i++) {
                float x = xv[i];
                if (dn) x = fmaxf((x - mean)*inv, 0.f);
                bsplit(x, ph.b[i], pl.b[i]);
            }
            int kof = cg*16 + h*8;
            *(uint4*)(smem + A_H + ce*80 + kof*2) = ph.u;
            *(uint4*)(smem + A_L + ce*80 + kof*2) = pl.u;
        }
        #pragma unroll
        for (int h = 0; h < 2; h++) {
            int kof = (cg + h*2)*8;
            *(uint4*)(smem + B_H + ce*80 + kof*2) = *(const uint4*)(WhB + (size_t)ce*K + k0 + kof);
            *(uint4*)(smem + B_L + ce*80 + kof*2) = *(const uint4*)(WlB + (size_t)ce*K + k0 + kof);
        }
        __syncthreads();
        #pragma unroll
        for (int kk = 0; kk < 32; kk += 16) {
            u32 ah[2][4], al[2][4];
            #pragma unroll
            for (int mt = 0; mt < 2; mt++) {
                u32 ra = sb + (u32)((wm*32 + mt*16 + (lane&15))*80 + (kk + ((lane>>4)<<3))*2);
                LDM4(ah[mt], A_H + ra);
                LDM4(al[mt], A_L + ra);
            }
            #pragma unroll
            for (int np = 0; np < 4; np++) {
                u32 rb = sb + (u32)((wn*64 + np*16 + (lane&7) + ((lane>>4)<<3))*80 + (kk + ((lane>>3)&1)*8)*2);
                u32 bh[4], bl[4];
                LDM4(bh, B_H + rb);
                LDM4(bl, B_L + rb);
                #pragma unroll
                for (int mt = 0; mt < 2; mt++) {
                    MMA(d[mt][np*2],   ah[mt], bh[0], bh[1]);
                    MMA(d[mt][np*2],   ah[mt], bl[0], bl[1]);
                    MMA(d[mt][np*2],   al[mt], bh[0], bh[1]);
                    MMA(d[mt][np*2+1], ah[mt], bh[2], bh[3]);
                    MMA(d[mt][np*2+1], ah[mt], bl[2], bl[3]);
                    MMA(d[mt][np*2+1], al[mt], bh[2], bh[3]);
                }
            }
        }
    }

    // ---- epilogue (Y row-major) ----
    const int quad = lane>>2, tc = (lane&3)*2;
    float s = 0.f, q = 0.f;
    #pragma unroll
    for (int mt = 0; mt < 2; mt++) {
        #pragma unroll
        for (int hf = 0; hf < 2; hf++) {
            int e = m0 + wm*32 + mt*16 + quad + hf*8;
            if (e >= E) continue;
            const float* gp = nullptr;
            if (gInit) gp = gInit + (size_t)g0[e]*256;
            float *ip = nullptr, *jp = nullptr;
            if (epi == 2) {
                ip = sc + (size_t)iI[e]*ldS;
                jp = sc + (size_t)jI[e]*ldS + 128;
            }
            float* yrow = Y + (size_t)e*ldY + oB;
            #pragma unroll
            for (int nt = 0; nt < 8; nt++) {
                int oL = wn*64 + nt*8 + tc;
                float x0 = d[mt][nt][hf*2+0];
                float x1 = d[mt][nt][hf*2+1];
                if (gp) { x0 += gp[oB + oL]; x1 += gp[oB + oL + 1]; }
                if (epi == 0) {
                    *(float2*)(yrow + oL) = make_float2(x0, x1);
                    s += x0 + x1; q += x0*x0 + x1*x1;
                } else {
                    float2 old = *(float2*)(yrow + oL);
                    old.x += 0.1f*x0; old.y += 0.1f*x1;
                    *(float2*)(yrow + oL) = old;
                    if (epi == 2) {
                        REDV2(ip + oL, x0, x1);
                        REDV2(jp + oL, x0, x1);
                    }
                }
            }
        }
    }
    if (statAcc) {
        float* rs = (float*)(smem + 40960); float* rq = rs + 256;
        __syncthreads();
        rs[tid] = s; rq[tid] = q;
        __syncthreads();
        for (int st = 128; st > 0; st >>= 1) {
            if (tid < st) { rs[tid] += rs[tid+st]; rq[tid] += rq[tid+st]; }
            __syncthreads();
        }
        if (tid == 0) { atomicAdd(statAcc, (double)rs[0]); atomicAdd(statAcc+1, (double)rq[0]); }
    }
}

// ---------- SIMT f32x2 GEMM (opening GEMMs only; channel-major X) ----------
__global__ void __launch_bounds__(256, 2)
mm4_kernel(int M, int Oact, int ldY3,
           const float* __restrict__ W0, const float* __restrict__ X0, int K0, int ld0, int ldW0,
           const double* __restrict__ normAcc, double cntInv, double* __restrict__ statAcc,
           float* __restrict__ Y, int epi)
{
    __shared__ __align__(16) ull   Wd[2][8][132];
    __shared__ __align__(16) float Xs[2][8][132];
    const int tid = threadIdx.x, m0 = blockIdx.x*128, wb = blockIdx.y*128;
    const int lane = tid&31, warp = tid>>5;
    const int rbase = (warp>>2)*64 + (lane>>2)*4;
    const int cbase = (warp&3)*32 + (lane&3)*4;
    const int kkS = tid>>5, mfS = (tid&31)*4;

    float mean = 0.f, inv = 0.f;
    const bool dn = (normAcc != nullptr);
    if (dn) {
        double mu = normAcc[0]*cntInv, va = normAcc[1]*cntInv - mu*mu;
        mean = (float)mu; inv = (float)rsqrt(va + 1e-5);
    }
    ull acc[8][4];
    #pragma unroll
    for (int r = 0; r < 8; r++) { acc[r][0]=acc[r][1]=acc[r][2]=acc[r][3]=0ull; }

    const int totT = K0 >> 3;
    auto ldg = [&](int t, float4& wv, float4& xv) {
        int k0 = t*8;
        wv = *(const float4*)(W0 + (size_t)(k0+kkS)*ldW0 + wb + mfS);
        int m = m0 + mfS;
        if (m < M) {
            float4 v = *(const float4*)(X0 + (size_t)(k0+kkS)*ld0 + m);
            if (dn) {
                v.x = fmaxf((v.x-mean)*inv, 0.f); v.y = fmaxf((v.y-mean)*inv, 0.f);
                v.z = fmaxf((v.z-mean)*inv, 0.f); v.w = fmaxf((v.w-mean)*inv, 0.f);
            }
            xv = v;
        } else xv = make_float4(0.f,0.f,0.f,0.f);
    };
    auto sts = [&](int b, const float4& wv, const float4& xv) {
        ull* wr = &Wd[b][kkS][mfS];
        wr[0]=dup2(wv.x); wr[1]=dup2(wv.y); wr[2]=dup2(wv.z); wr[3]=dup2(wv.w);
        *(float4*)&Xs[b][kkS][mfS] = xv;
    };
    { float4 wv, xv; ldg(0, wv, xv); sts(0, wv, xv); }
    __syncthreads();
    float4 wpv, xpv;
    for (int t = 0; t < totT; t++) {
        const int cur = t&1; const bool more = (t+1 < totT);
        if (more) ldg(t+1, wpv, xpv);
        #pragma unroll
        for (int kk = 0; kk < 8; kk++) {
            ulonglong2 w01 = *(const ulonglong2*)&Wd[cur][kk][rbase];
            ulonglong2 w23 = *(const ulonglong2*)&Wd[cur][kk][rbase+2];
            ulonglong2 w45 = *(const ulonglong2*)&Wd[cur][kk][rbase+32];
            ulonglong2 w67 = *(const ulonglong2*)&Wd[cur][kk][rbase+34];
            ulonglong2 xa = *(const ulonglong2*)&Xs[cur][kk][cbase];
            ulonglong2 xb = *(const ulonglong2*)&Xs[cur][kk][cbase+16];
            ffma2(acc[0][0],w01.x,xa.x); ffma2(acc[0][1],w01.x,xa.y); ffma2(acc[0][2],w01.x,xb.x); ffma2(acc[0][3],w01.x,xb.y);
            ffma2(acc[1][0],w01.y,xa.x); ffma2(acc[1][1],w01.y,xa.y); ffma2(acc[1][2],w01.y,xb.x); ffma2(acc[1][3],w01.y,xb.y);
            ffma2(acc[2][0],w23.x,xa.x); ffma2(acc[2][1],w23.x,xa.y); ffma2(acc[2][2],w23.x,xb.x); ffma2(acc[2][3],w23.x,xb.y);
            ffma2(acc[3][0],w23.y,xa.x); ffma2(acc[3][1],w23.y,xa.y); ffma2(acc[3][2],w23.y,xb.x); ffma2(acc[3][3],w23.y,xb.y);
            ffma2(acc[4][0],w45.x,xa.x); ffma2(acc[4][1],w45.x,xa.y); ffma2(acc[4][2],w45.x,xb.x); ffma2(acc[4][3],w45.x,xb.y);
            ffma2(acc[5][0],w45.y,xa.x); ffma2(acc[5][1],w45.y,xa.y); ffma2(acc[5][2],w45.y,xb.x); ffma2(acc[5][3],w45.y,xb.y);
            ffma2(acc[6][0],w67.x,xa.x); ffma2(acc[6][1],w67.x,xa.y); ffma2(acc[6][2],w67.x,xb.x); ffma2(acc[6][3],w67.x,xb.y);
            ffma2(acc[7][0],w67.y,xa.x); ffma2(acc[7][1],w67.y,xa.y); ffma2(acc[7][2],w67.y,xb.x); ffma2(acc[7][3],w67.y,xb.y);
        }
        if (more) sts(cur^1, wpv, xpv);
        __syncthreads();
    }
    if (statAcc) {
        float s = 0.f, q = 0.f;
        #pragma unroll
        for (int r = 0; r < 8; r++)
            #pragma unroll
            for (int cg = 0; cg < 2; cg++)
                if (m0 + cbase + cg*16 < M) {
                    float2 a = f2of(acc[r][cg*2]), b = f2of(acc[r][cg*2+1]);
                    s += a.x+a.y+b.x+b.y; q += a.x*a.x+a.y*a.y+b.x*b.x+b.y*b.y;
                }
        __syncthreads();
        float* rs = (float*)Wd; float* rq = rs + 256;
        rs[tid] = s; rq[tid] = q;
        __syncthreads();
        for (int st = 128; st > 0; st >>= 1) {
            if (tid < st) { rs[tid] += rs[tid+st]; rq[tid] += rq[tid+st]; }
            __syncthreads();
        }
        if (tid == 0) { atomicAdd(statAcc,(double)rs[0]); atomicAdd(statAcc+1,(double)rq[0]); }
    }
    if (epi == 3) {
        #pragma unroll
        for (int j = 0; j < 4; j++)
            #pragma unroll
            for (int h = 0; h < 2; h++) {
                int c = m0 + cbase + (j>>1)*16 + (j&1)*2 + h;
                if (c >= M) continue;
                float4 v0, v1;
                if (h == 0) {
                    v0 = make_float4(f2of(acc[0][j]).x, f2of(acc[1][j]).x, f2of(acc[2][j]).x, f2of(acc[3][j]).x);
                    v1 = make_float4(f2of(acc[4][j]).x, f2of(acc[5][j]).x, f2of(acc[6][j]).x, f2of(acc[7][j]).x);
                } else {
                    v0 = make_float4(f2of(acc[0][j]).y, f2of(acc[1][j]).y, f2of(acc[2][j]).y, f2of(acc[3][j]).y);
                    v1 = make_float4(f2of(acc[4][j]).y, f2of(acc[5][j]).y, f2of(acc[6][j]).y, f2of(acc[7][j]).y);
                }
                float* dst = Y + (size_t)c*ldY3 + wb + rbase;
                *(float4*)dst = v0; *(float4*)(dst+32) = v1;
            }
        return;
    }
    #pragma unroll
    for (int r = 0; r < 8; r++) {
        int o = wb + ((r < 4) ? (rbase + r) : (rbase + 28 + r));
        if (o >= Oact) continue;
        #pragma unroll
        for (int cg = 0; cg < 2; cg++) {
            int c = m0 + cbase + cg*16;
            if (c >= M) continue;
            float2 p0 = f2of(acc[r][cg*2]), p1 = f2of(acc[r][cg*2+1]);
            *(float4*)(Y + (size_t)o*M + c) = make_float4(p0.x, p0.y, p1.x, p1.y);
        }
    }
}

static inline void mm_launch(int M, int ldY3,
    const float* W0, const float* X0, int K0, int ld0, int ldW0,
    const double* nA, double ci, double* sA, float* Y, int epi)
{
    dim3 g((M+127)/128, 1);
    mm4_kernel<<<g, 256>>>(M, 128, ldY3, W0, X0, K0, ld0, ldW0, nA, ci, sA, Y, epi);
}
static inline void hmma_launch(int M, int O, int K, int ldX, int ldY,
    const __nv_bfloat16* Wh, const __nv_bfloat16* Wl, const float* X,
    const float* gI, const int* g0, const double* nA, double ci, double* sA,
    float* Y, int epi, float* sc, int ldS, const int* iI, const int* jI)
{
    dim3 g((M+127)/128, O/128);
    hmma_kernel<<<g, 256>>>(M, K, ldX, ldY, Wh, Wl, X, gI, g0, nA, ci, sA, Y, epi, sc, ldS, iI, jI);
}

extern "C" void kernel_launch(void* const* d_in, const int* in_sizes, int n_in,
                              void* d_out, int out_size)
{
    if (n_in < 13) return;
    const float* xn_in = (const float*)d_in[0];
    const float* xe_in = (const float*)d_in[1];
    const int* iInd = (const int*)d_in[2];
    const int* jInd = (const int*)d_in[3];
    const float* K1No = (const float*)d_in[4];
    const float* K2No = (const float*)d_in[5];
    const float* K1Eo = (const float*)d_in[6];
    const float* K2Eo = (const float*)d_in[7];
    const float* KNout= (const float*)d_in[8];
    const float* KE1  = (const float*)d_in[9];
    const float* KE2  = (const float*)d_in[10];
    const float* KN1  = (const float*)d_in[11];
    const float* KN2  = (const float*)d_in[12];
    int N = in_sizes[0]/32, E = in_sizes[1]/32;

    float *t,*xe,*sN,*yAT,*k1n,*k2n,*k1e;
    __nv_bfloat16 *bhN1,*blN1,*bhN2,*blN2,*bhEa,*blEa,*bhE1,*blE1,*bhE2,*blE2,*bhOE,*blOE,*bhKO,*blKO;
    double* acc;
    cudaGetSymbolAddress((void**)&t,g_t);     cudaGetSymbolAddress((void**)&xe,g_xe);
    cudaGetSymbolAddress((void**)&sN,g_sN);   cudaGetSymbolAddress((void**)&yAT,g_yAT);
    cudaGetSymbolAddress((void**)&k1n,g_k1n); cudaGetSymbolAddress((void**)&k2n,g_k2n);
    cudaGetSymbolAddress((void**)&k1e,g_k1e);
    cudaGetSymbolAddress((void**)&bhN1,g_bhN1); cudaGetSymbolAddress((void**)&blN1,g_blN1);
    cudaGetSymbolAddress((void**)&bhN2,g_bhN2); cudaGetSymbolAddress((void**)&blN2,g_blN2);
    cudaGetSymbolAddress((void**)&bhEa,g_bhEa); cudaGetSymbolAddress((void**)&blEa,g_blEa);
    cudaGetSymbolAddress((void**)&bhE1,g_bhE1); cudaGetSymbolAddress((void**)&blE1,g_blE1);
    cudaGetSymbolAddress((void**)&bhE2,g_bhE2); cudaGetSymbolAddress((void**)&blE2,g_blE2);
    cudaGetSymbolAddress((void**)&bhOE,g_bhOE); cudaGetSymbolAddress((void**)&blOE,g_blOE);
    cudaGetSymbolAddress((void**)&bhKO,g_bhKO); cudaGetSymbolAddress((void**)&blKO,g_blKO);
    cudaGetSymbolAddress((void**)&acc,g_acc);

    float* out = (float*)d_out;
    float* xe_out = out + (size_t)64*N;
    float* xnR = sN + 256;   // xn rows live at sN[n][256:384]

    cudaMemsetAsync(acc, 0, 20*sizeof(double), 0);
    prep_kernelA<<<(4*256*384+255)/256, 256>>>(KE1, KN1, KE2, KN2);
    prep_kernelB<<<(128*128+255)/256, 256>>>(K1No, K2No, K1Eo, K2Eo, KNout);

    // opening node: t[128][N] = k1n@xn_in (stats acc0); xn rows = k2n@relu(norm t) via epi3
    mm_launch(N, 0,   k1n, xn_in, 32, N, 128, nullptr, 0.0, acc+0, t, 0);
    mm_launch(N, 384, k2n, t, 128, N, 128, acc+0, 1.0/(128.0*N), nullptr, xnR, 3);

    // opening edge: t[E][128] edge-major via epi3 (stats acc2); xe = OE @ relu(norm t) via hmma
    mm_launch(E, 128, k1e, xe_in, 32, E, 128, nullptr, 0.0, acc+2, t, 3);
    hmma_launch(E, 128, 128, 128, 128, bhOE, blOE, t, nullptr, nullptr, acc+2, 1.0/(128.0*E), nullptr,
                xe, 0, nullptr, 0, nullptr, nullptr);

    for (int l = 0; l < 4; l++) {
        double* accE = acc + 4 + 4*l;
        double* accN = acc + 6 + 4*l;
        // yAT[n][256] = wEa @ xn
        hmma_launch(N, 256, 128, 384, 256, bhEa + (size_t)l*256*128, blEa + (size_t)l*256*128, xnR,
                    nullptr, nullptr, nullptr, 0.0, nullptr, yAT, 0, nullptr, 0, nullptr, nullptr);
        // edge mm1': t[e][256] = gather(yAT,iInd) + wEb @ xe  (+stats accE)
        hmma_launch(E, 256, 128, 128, 256, bhE1 + (size_t)l*256*128, blE1 + (size_t)l*256*128, xe,
                    yAT, iInd, nullptr, 0.0, accE, t, 0, nullptr, 0, nullptr, nullptr);
        // zero si|sj
        zeroS<<<(N*64+255)/256, 256>>>(sN, N);
        // edge mm2: xe += 0.1*(KE2 @ relu(norm t)); red.v2 scatter into sN rows
        hmma_launch(E, 128, 256, 256, 128, bhE2 + (size_t)l*128*256, blE2 + (size_t)l*128*256, t,
                    nullptr, nullptr, accE, 1.0/(256.0*E), nullptr, xe, 2, sN, 384, iInd, jInd);
        // node mm1: t[n][256] = N1 @ sN rows (K=384)  (+stats accN)
        hmma_launch(N, 256, 384, 384, 256, bhN1 + (size_t)l*256*384, blN1 + (size_t)l*256*384, sN,
                    nullptr, nullptr, nullptr, 0.0, accN, t, 0, nullptr, 0, nullptr, nullptr);
        // node mm2: xn += 0.1*(N2 @ relu(norm t))
        hmma_launch(N, 128, 256, 256, 384, bhN2 + (size_t)l*128*256, blN2 + (size_t)l*128*256, t,
                    nullptr, nullptr, accN, 1.0/(256.0*N), nullptr, xnR, 1, nullptr, 0, nullptr, nullptr);
    }
    // final: tmp[n][128] = KO @ xn (rows 64+ are zero-weight); transpose to out[64][N]
    hmma_launch(N, 128, 128, 384, 128, bhKO, blKO, xnR,
                nullptr, nullptr, nullptr, 0.0, nullptr, yAT, 0, nullptr, 0, nullptr, nullptr);
    {
        dim3 tg((N+31)/32, 2), tb(32, 8);
        transposeNC<<<tg, tb>>>(yAT, out, N, 128, 64);
    }
    {
        dim3 tg((E+31)/32, 4), tb(32, 8);
        transposeNC<<<tg, tb>>>(xe, xe_out, E, 128, 128);
    }
}